// round 11
// baseline (speedup 1.0000x reference)
#include <cuda_runtime.h>
#include <cuda_bf16.h>
#include <cstdint>

#define Q     65536
#define HH    256
#define WW    256
#define NPIX  (HH*WW)    /* 65536 */
#define MROWS (4*Q)      /* 262144 */
#define KC    288        /* conv GEMM K: 9 stages of 32 */
#define NHID  256

typedef unsigned int u32;

// ---------------- scratch (device globals; no allocation allowed) ----------
__device__ __nv_bfloat16 g_XCh[(size_t)NPIX * KC];
__device__ __nv_bfloat16 g_XCl[(size_t)NPIX * KC];
__device__ float         g_G  [(size_t)NPIX * NHID];
__device__ __nv_bfloat16 g_HAh[(size_t)MROWS * NHID];
__device__ __nv_bfloat16 g_HAl[(size_t)MROWS * NHID];
__device__ __nv_bfloat16 g_HBh[(size_t)MROWS * NHID];
__device__ __nv_bfloat16 g_HBl[(size_t)MROWS * NHID];
__device__ float g_PRED[(size_t)MROWS * 3];
__device__ float g_AREA[MROWS];
__device__ int    g_RIP[MROWS];
__device__ float4 g_RIV[MROWS];
__device__ __nv_bfloat16 g_W1h[256 * KC],  g_W1l[256 * KC];
__device__ __nv_bfloat16 g_W2h[256 * 256], g_W2l[256 * 256];
__device__ __nv_bfloat16 g_W3h[256 * 256], g_W3l[256 * 256];
__device__ __nv_bfloat16 g_W4h[256 * 256], g_W4l[256 * 256];

// ---------------- helpers ---------------------------------------------------
__device__ __forceinline__ u32 pack2(float x, float y) {
    __nv_bfloat162 t = __floats2bfloat162_rn(x, y);
    return *reinterpret_cast<u32*>(&t);
}
__device__ __forceinline__ void mma_bf16(float* d, const u32* a, const u32* b) {
    asm("mma.sync.aligned.m16n8k16.row.col.f32.bf16.bf16.f32 "
        "{%0,%1,%2,%3}, {%4,%5,%6,%7}, {%8,%9}, {%0,%1,%2,%3};"
        : "+f"(d[0]), "+f"(d[1]), "+f"(d[2]), "+f"(d[3])
        : "r"(a[0]), "r"(a[1]), "r"(a[2]), "r"(a[3]), "r"(b[0]), "r"(b[1]));
}
__device__ __forceinline__ void ldsm4(u32* r, const __nv_bfloat16* p) {
    u32 a = (u32)__cvta_generic_to_shared(p);
    asm volatile("ldmatrix.sync.aligned.m8n8.x4.shared.b16 {%0,%1,%2,%3}, [%4];"
                 : "=r"(r[0]), "=r"(r[1]), "=r"(r[2]), "=r"(r[3]) : "r"(a));
}
__device__ __forceinline__ void cp16(__nv_bfloat16* s, const __nv_bfloat16* g) {
    u32 sa = (u32)__cvta_generic_to_shared(s);
    asm volatile("cp.async.cg.shared.global [%0], [%1], 16;" :: "r"(sa), "l"(g));
}
__device__ __forceinline__ void cp_commit() {
    asm volatile("cp.async.commit_group;" ::: "memory");
}
template<int N> __device__ __forceinline__ void cp_wait() {
    asm volatile("cp.async.wait_group %0;" :: "n"(N) : "memory");
}

// ---------------- W prep (all 4 weights in ONE launch) ----------------------
__global__ void prep_all_kernel(const float* __restrict__ w1,
                                const float* __restrict__ w2,
                                const float* __restrict__ w3,
                                const float* __restrict__ w4) {
    int i = blockIdx.x * 256 + threadIdx.x;
    const int S1 = 256 * KC;
    const int S  = 256 * 256;
    const float* w;
    __nv_bfloat16 *hi, *lo;
    int Kpad, idx;
    if (i < S1)              { w = w1; hi = g_W1h; lo = g_W1l; Kpad = KC;  idx = i; }
    else if (i < S1 + S)     { w = w2; hi = g_W2h; lo = g_W2l; Kpad = 256; idx = i - S1; }
    else if (i < S1 + 2 * S) { w = w3; hi = g_W3h; lo = g_W3l; Kpad = 256; idx = i - S1 - S; }
    else if (i < S1 + 3 * S) { w = w4; hi = g_W4h; lo = g_W4l; Kpad = 256; idx = i - S1 - 2 * S; }
    else return;
    int n = idx / Kpad, k = idx - n * Kpad;
    float v = w[(size_t)k * 256 + n];
    __nv_bfloat16 h = __float2bfloat16(v);
    hi[idx] = h;
    lo[idx] = __float2bfloat16(v - __bfloat162float(h));
}

// ---------------- im2col: per-pixel 3x3 reflect patch -> bf16 hi/lo --------
__global__ void im2col_kernel(const float* __restrict__ F) {
    const int p = blockIdx.x;
    const int t = threadIdx.x;         // 0..287
    const int y0 = p >> 8, x0 = p & 255;
    int c  = t / 9;
    int k  = t - c * 9;
    int di = k / 3, dj = k - di * 3;
    int y = y0 + di - 1;
    int x = x0 + dj - 1;
    y = (y < 0) ? -y : ((y >= HH) ? 2 * HH - 2 - y : y);
    x = (x < 0) ? -x : ((x >= WW) ? 2 * WW - 2 - x : x);
    float v = F[(size_t)c * NPIX + y * WW + x];
    __nv_bfloat16 h = __float2bfloat16(v);
    g_XCh[(size_t)p * KC + t] = h;
    g_XCl[(size_t)p * KC + t] = __float2bfloat16(v - __bfloat162float(h));
}

// ---------------- rowinfo: per-(q,s) scalars, once -------------------------
__global__ __launch_bounds__(256)
void rowinfo_kernel(const float* __restrict__ loc,
                    const float* __restrict__ cell) {
    int i = blockIdx.x * 256 + threadIdx.x;
    int q = i & (Q - 1);
    int s = i >> 16;

    float l0 = loc[(size_t)q * 2 + 0];
    float l1 = loc[(size_t)q * 2 + 1];
    float sy = (s & 2) ? 1.f : -1.f;
    float sx = (s & 1) ? 1.f : -1.f;
    float ly = l0 + sy * (1.f / HH) + 1e-6f;
    float lx = l1 + sx * (1.f / WW) + 1e-6f;
    ly = fminf(fmaxf(ly, -1.f + 1e-6f), 1.f - 1e-6f);
    lx = fminf(fmaxf(lx, -1.f + 1e-6f), 1.f - 1e-6f);
    int iy = (int)rintf(((ly + 1.f) * HH - 1.f) * 0.5f);
    int ix = (int)rintf(((lx + 1.f) * WW - 1.f) * 0.5f);
    iy = min(max(iy, 0), HH - 1);
    ix = min(max(ix, 0), WW - 1);
    float qy = -1.f + (2.f * iy + 1.f) / HH;
    float qx = -1.f + (2.f * ix + 1.f) / WW;
    float rel0 = (l0 - qy) * HH;
    float rel1 = (l1 - qx) * WW;
    float c0 = cell[(size_t)q * 2 + 0] * HH;
    float c1 = cell[(size_t)q * 2 + 1] * WW;

    g_RIP[i]  = iy * WW + ix;
    g_RIV[i]  = make_float4(rel0, rel1, c0, c1);
    g_AREA[i] = fabsf(rel0 * rel1) + 1e-9f;
}

// ---------------- combine2: H1 = relu(G[p] + rank-4 + b1) -> bf16 hi/lo ----
__global__ __launch_bounds__(256)
void combine2_kernel(const float* __restrict__ w1,
                     const float* __restrict__ b1,
                     __nv_bfloat16* __restrict__ Hh,
                     __nv_bfloat16* __restrict__ Hl) {
    __shared__ float sw[5 * 256];
    const int tid = threadIdx.x;
    for (int i = tid; i < 1024; i += 256) sw[i] = w1[288 * 256 + i];
    if (tid < 256) sw[1024 + tid] = b1[tid];
    __syncthreads();

    const size_t row = (size_t)blockIdx.x * 4 + (tid >> 6);
    const int c4 = (tid & 63) * 4;

    const int p = g_RIP[row];
    const float4 rc = g_RIV[row];

    float4 g  = *reinterpret_cast<const float4*>(g_G + (size_t)p * NHID + c4);
    float4 wA = *reinterpret_cast<const float4*>(sw + c4);
    float4 wB = *reinterpret_cast<const float4*>(sw + 256 + c4);
    float4 wC = *reinterpret_cast<const float4*>(sw + 512 + c4);
    float4 wD = *reinterpret_cast<const float4*>(sw + 768 + c4);
    float4 bb = *reinterpret_cast<const float4*>(sw + 1024 + c4);

    float v[4];
    v[0] = fmaxf(g.x + rc.x * wA.x + rc.y * wB.x + rc.z * wC.x + rc.w * wD.x + bb.x, 0.f);
    v[1] = fmaxf(g.y + rc.x * wA.y + rc.y * wB.y + rc.z * wC.y + rc.w * wD.y + bb.y, 0.f);
    v[2] = fmaxf(g.z + rc.x * wA.z + rc.y * wB.z + rc.z * wC.z + rc.w * wD.z + bb.z, 0.f);
    v[3] = fmaxf(g.w + rc.x * wA.w + rc.y * wB.w + rc.z * wC.w + rc.w * wD.w + bb.w, 0.f);

    float h[4];
#pragma unroll
    for (int j = 0; j < 4; ++j) h[j] = __bfloat162float(__float2bfloat16(v[j]));

    size_t off = row * NHID + c4;
    *reinterpret_cast<uint2*>(Hh + off) = make_uint2(pack2(h[0], h[1]), pack2(h[2], h[3]));
    *reinterpret_cast<uint2*>(Hl + off) = make_uint2(pack2(v[0] - h[0], v[1] - h[1]),
                                                     pack2(v[2] - h[2], v[3] - h[3]));
}

// ---------------- HMMA bf16-3x GEMM, 64x128 tile, 4 warps, 4 CTAs/SM -------
#define SST    40
#define APLANE (64  * SST)     /* 2560 elem */
#define BPLANE (128 * SST)     /* 5120 elem */
#define STAGE  (2 * APLANE + 2 * BPLANE)   /* 15360 elem */
#define SMEMB  (2 * STAGE * 2) /* 61440 B */

template<int K>
__device__ __forceinline__ void load_stage(
        __nv_bfloat16* st,
        const __nv_bfloat16* __restrict__ Ah, const __nv_bfloat16* __restrict__ Al,
        const __nv_bfloat16* __restrict__ Bh, const __nv_bfloat16* __restrict__ Bl,
        int m0, int n0, int kb, int tid) {
    // A: 64 rows x 32 cols, 2 planes
#pragma unroll
    for (int i = 0; i < 2; ++i) {
        int chunk = tid + i * 128;          // 0..255
        int row = chunk >> 2;
        int c8  = (chunk & 3) << 3;
        size_t ga = (size_t)(m0 + row) * K + kb + c8;
        int so = row * SST + c8;
        cp16(st + so,          Ah + ga);
        cp16(st + APLANE + so, Al + ga);
    }
    // B: 128 rows x 32 cols, 2 planes
#pragma unroll
    for (int i = 0; i < 4; ++i) {
        int chunk = tid + i * 128;          // 0..511
        int row = chunk >> 2;
        int c8  = (chunk & 3) << 3;
        size_t gb = (size_t)(n0 + row) * K + kb + c8;
        int so = row * SST + c8;
        cp16(st + 2 * APLANE + so,          Bh + gb);
        cp16(st + 2 * APLANE + BPLANE + so, Bl + gb);
    }
}

// MODE: 0 = fp32 raw out; 1 = bias+relu -> bf16 hi/lo; 2 = bias+relu -> dot w5 -> atomicAdd
template<int K, int MODE>
__global__ __launch_bounds__(128, 4)
void hmma_gemm(const __nv_bfloat16* __restrict__ Ah,
               const __nv_bfloat16* __restrict__ Al,
               const __nv_bfloat16* __restrict__ Bh,
               const __nv_bfloat16* __restrict__ Bl,
               const float* __restrict__ bias,
               void* __restrict__ Cout,
               __nv_bfloat16* __restrict__ Clo,
               const float* __restrict__ w5) {
    extern __shared__ __nv_bfloat16 smem[];

    const int tid  = threadIdx.x;
    const int lane = tid & 31;
    const int wid  = tid >> 5;        // 0..3
    const int wm   = wid & 1;         // 2 m-groups of 32 rows
    const int wn   = wid >> 1;        // 2 n-groups of 64 cols
    const int m0   = blockIdx.y * 64;
    const int n0   = blockIdx.x * 128;
    const int lr   = lane >> 2;
    const int lq   = lane & 3;
    const int grp  = lane >> 3;
    const int rr   = lane & 7;

    const int a_row = wm * 32 + (grp & 1) * 8 + rr;
    const int a_kb  = (grp >> 1) * 8;
    const int b_row = wn * 64 + (grp >> 1) * 8 + rr;
    const int b_kb  = (grp & 1) * 8;

    float acc[2][8][4];
#pragma unroll
    for (int i = 0; i < 2; ++i)
#pragma unroll
        for (int j = 0; j < 8; ++j)
#pragma unroll
            for (int c = 0; c < 4; ++c) acc[i][j][c] = 0.f;

    constexpr int S = K / 32;
    load_stage<K>(smem, Ah, Al, Bh, Bl, m0, n0, 0, tid);
    cp_commit();

    for (int s = 0; s < S; ++s) {
        if (s + 1 < S) {
            load_stage<K>(smem + ((s + 1) & 1) * STAGE, Ah, Al, Bh, Bl,
                          m0, n0, (s + 1) * 32, tid);
            cp_commit();
            cp_wait<1>();
        } else {
            cp_wait<0>();
        }
        __syncthreads();

        const __nv_bfloat16* sAh = smem + (s & 1) * STAGE;
        const __nv_bfloat16* sAl = sAh + APLANE;
        const __nv_bfloat16* sBh = sAh + 2 * APLANE;
        const __nv_bfloat16* sBl = sBh + BPLANE;

#pragma unroll
        for (int ks = 0; ks < 32; ks += 16) {
            u32 af[2][2][4];
#pragma unroll
            for (int ti = 0; ti < 2; ++ti) {
                ldsm4(af[ti][0], sAh + (a_row + ti * 16) * SST + ks + a_kb);
                ldsm4(af[ti][1], sAl + (a_row + ti * 16) * SST + ks + a_kb);
            }
#pragma unroll
            for (int jp = 0; jp < 4; ++jp) {
                u32 bh[4], bl[4];
                ldsm4(bh, sBh + (b_row + jp * 16) * SST + ks + b_kb);
                ldsm4(bl, sBl + (b_row + jp * 16) * SST + ks + b_kb);
#pragma unroll
                for (int ti = 0; ti < 2; ++ti) {
                    mma_bf16(acc[ti][2 * jp],     af[ti][0], bh);
                    mma_bf16(acc[ti][2 * jp],     af[ti][0], bl);
                    mma_bf16(acc[ti][2 * jp],     af[ti][1], bh);
                    mma_bf16(acc[ti][2 * jp + 1], af[ti][0], bh + 2);
                    mma_bf16(acc[ti][2 * jp + 1], af[ti][0], bl + 2);
                    mma_bf16(acc[ti][2 * jp + 1], af[ti][1], bh + 2);
                }
            }
        }
        __syncthreads();
    }

    // ---- epilogue ----
    if (MODE == 0) {
        float* C = (float*)Cout;
#pragma unroll
        for (int ti = 0; ti < 2; ++ti) {
            int row0 = m0 + wm * 32 + ti * 16 + lr;
#pragma unroll
            for (int tj = 0; tj < 8; ++tj) {
                int col0 = n0 + wn * 64 + tj * 8 + lq * 2;
#pragma unroll
                for (int half = 0; half < 2; ++half) {
                    size_t off = (size_t)(row0 + half * 8) * NHID + col0;
                    *reinterpret_cast<float2*>(C + off) =
                        make_float2(acc[ti][tj][half * 2 + 0],
                                    acc[ti][tj][half * 2 + 1]);
                }
            }
        }
    } else if (MODE == 1) {
        __nv_bfloat16* Chi = (__nv_bfloat16*)Cout;
#pragma unroll
        for (int ti = 0; ti < 2; ++ti) {
            int row0 = m0 + wm * 32 + ti * 16 + lr;
#pragma unroll
            for (int tj = 0; tj < 8; ++tj) {
                int col0 = n0 + wn * 64 + tj * 8 + lq * 2;
                float b0 = bias[col0], b1 = bias[col0 + 1];
#pragma unroll
                for (int half = 0; half < 2; ++half) {
                    size_t off = (size_t)(row0 + half * 8) * NHID + col0;
                    float v0 = fmaxf(acc[ti][tj][half * 2 + 0] + b0, 0.f);
                    float v1 = fmaxf(acc[ti][tj][half * 2 + 1] + b1, 0.f);
                    float h0 = __bfloat162float(__float2bfloat16(v0));
                    float h1 = __bfloat162float(__float2bfloat16(v1));
                    *reinterpret_cast<u32*>(Chi + off) = pack2(h0, h1);
                    *reinterpret_cast<u32*>(Clo + off) = pack2(v0 - h0, v1 - h1);
                }
            }
        }
    } else {
        float part[2][2][3];
#pragma unroll
        for (int ti = 0; ti < 2; ++ti)
#pragma unroll
            for (int h = 0; h < 2; ++h)
#pragma unroll
                for (int c = 0; c < 3; ++c) part[ti][h][c] = 0.f;

#pragma unroll
        for (int tj = 0; tj < 8; ++tj) {
            int col0 = n0 + wn * 64 + tj * 8 + lq * 2;
            float b0 = bias[col0], b1 = bias[col0 + 1];
            float w50[3], w51[3];
#pragma unroll
            for (int c = 0; c < 3; ++c) {
                w50[c] = w5[col0 * 3 + c];
                w51[c] = w5[(col0 + 1) * 3 + c];
            }
#pragma unroll
            for (int ti = 0; ti < 2; ++ti)
#pragma unroll
                for (int half = 0; half < 2; ++half) {
                    float v0 = fmaxf(acc[ti][tj][half * 2 + 0] + b0, 0.f);
                    float v1 = fmaxf(acc[ti][tj][half * 2 + 1] + b1, 0.f);
#pragma unroll
                    for (int c = 0; c < 3; ++c)
                        part[ti][half][c] += v0 * w50[c] + v1 * w51[c];
                }
        }
#pragma unroll
        for (int ti = 0; ti < 2; ++ti)
#pragma unroll
            for (int h = 0; h < 2; ++h)
#pragma unroll
                for (int c = 0; c < 3; ++c) {
                    float v = part[ti][h][c];
                    v += __shfl_xor_sync(0xffffffffu, v, 1);
                    v += __shfl_xor_sync(0xffffffffu, v, 2);
                    part[ti][h][c] = v;
                }
        float* sp = reinterpret_cast<float*>(smem);   // [2][64][3] = 384 floats
        if (lq == 0) {
#pragma unroll
            for (int ti = 0; ti < 2; ++ti)
#pragma unroll
                for (int h = 0; h < 2; ++h) {
                    int row = wm * 32 + ti * 16 + h * 8 + lr;
#pragma unroll
                    for (int c = 0; c < 3; ++c)
                        sp[(wn * 64 + row) * 3 + c] = part[ti][h][c];
                }
        }
        __syncthreads();
        for (int i = tid; i < 192; i += 128) {
            float v = sp[i] + sp[192 + i];
            atomicAdd(&g_PRED[(size_t)(m0 + i / 3) * 3 + (i % 3)], v);
        }
    }
}

// ---------------- output combine --------------------------------------------
__global__ __launch_bounds__(256)
void out_combine(const float* __restrict__ b5, float* __restrict__ out) {
    int q = blockIdx.x * 256 + threadIdx.x;
    float ar[4], tot = 0.f;
#pragma unroll
    for (int s = 0; s < 4; ++s) { ar[s] = g_AREA[(size_t)s * Q + q]; tot += ar[s]; }
    float r0 = 0.f, r1 = 0.f, r2 = 0.f;
#pragma unroll
    for (int s = 0; s < 4; ++s) {
        float wgt = ar[3 - s] / tot;
        size_t base = ((size_t)s * Q + q) * 3;
        r0 += (g_PRED[base + 0] + b5[0]) * wgt;
        r1 += (g_PRED[base + 1] + b5[1]) * wgt;
        r2 += (g_PRED[base + 2] + b5[2]) * wgt;
    }
    out[(size_t)q * 3 + 0] = r0;
    out[(size_t)q * 3 + 1] = r1;
    out[(size_t)q * 3 + 2] = r2;
}

// ---------------- launch ----------------------------------------------------
extern "C" void kernel_launch(void* const* d_in, const int* in_sizes, int n_in,
                              void* d_out, int out_size) {
    const float* F    = (const float*)d_in[0];
    const float* loc  = (const float*)d_in[1];
    const float* cell = (const float*)d_in[2];
    const float* w1 = (const float*)d_in[3];
    const float* b1 = (const float*)d_in[4];
    const float* w2 = (const float*)d_in[5];
    const float* b2 = (const float*)d_in[6];
    const float* w3 = (const float*)d_in[7];
    const float* b3 = (const float*)d_in[8];
    const float* w4 = (const float*)d_in[9];
    const float* b4 = (const float*)d_in[10];
    const float* w5 = (const float*)d_in[11];
    const float* b5 = (const float*)d_in[12];
    float* out = (float*)d_out;

    __nv_bfloat16 *XCh, *XCl, *HAh, *HAl, *HBh, *HBl;
    __nv_bfloat16 *W1h, *W1l, *W2h, *W2l, *W3h, *W3l, *W4h, *W4l;
    float *G, *PRED;
    cudaGetSymbolAddress((void**)&XCh, g_XCh); cudaGetSymbolAddress((void**)&XCl, g_XCl);
    cudaGetSymbolAddress((void**)&G,   g_G);
    cudaGetSymbolAddress((void**)&PRED, g_PRED);
    cudaGetSymbolAddress((void**)&HAh, g_HAh); cudaGetSymbolAddress((void**)&HAl, g_HAl);
    cudaGetSymbolAddress((void**)&HBh, g_HBh); cudaGetSymbolAddress((void**)&HBl, g_HBl);
    cudaGetSymbolAddress((void**)&W1h, g_W1h); cudaGetSymbolAddress((void**)&W1l, g_W1l);
    cudaGetSymbolAddress((void**)&W2h, g_W2h); cudaGetSymbolAddress((void**)&W2l, g_W2l);
    cudaGetSymbolAddress((void**)&W3h, g_W3h); cudaGetSymbolAddress((void**)&W3l, g_W3l);
    cudaGetSymbolAddress((void**)&W4h, g_W4h); cudaGetSymbolAddress((void**)&W4l, g_W4l);

    cudaFuncSetAttribute(hmma_gemm<KC, 0>,
        cudaFuncAttributeMaxDynamicSharedMemorySize, SMEMB);
    cudaFuncSetAttribute(hmma_gemm<256, 1>,
        cudaFuncAttributeMaxDynamicSharedMemorySize, SMEMB);
    cudaFuncSetAttribute(hmma_gemm<256, 2>,
        cudaFuncAttributeMaxDynamicSharedMemorySize, SMEMB);

    cudaMemsetAsync(PRED, 0, (size_t)MROWS * 3 * sizeof(float));

    const int PREP_ELEMS = 256 * KC + 3 * 256 * 256;
    prep_all_kernel<<<(PREP_ELEMS + 255) / 256, 256>>>(w1, w2, w3, w4);

    im2col_kernel<<<NPIX, KC>>>(F);
    rowinfo_kernel<<<MROWS / 256, 256>>>(loc, cell);

    // conv GEMM: G[65536,256] = XC @ W1[0:288]^T
    hmma_gemm<KC, 0><<<dim3(2, NPIX / 64), 128, SMEMB>>>(
        XCh, XCl, W1h, W1l, nullptr, G, nullptr, nullptr);

    combine2_kernel<<<MROWS / 4, 256>>>(w1, b1, HAh, HAl);

    dim3 ggrid(2, MROWS / 64);
    hmma_gemm<256, 1><<<ggrid, 128, SMEMB>>>(HAh, HAl, W2h, W2l, b2, HBh, HBl, nullptr);
    hmma_gemm<256, 1><<<ggrid, 128, SMEMB>>>(HBh, HBl, W3h, W3l, b3, HAh, HAl, nullptr);
    hmma_gemm<256, 2><<<ggrid, 128, SMEMB>>>(HAh, HAl, W4h, W4l, b4, nullptr, nullptr, w5);

    out_combine<<<Q / 256, 256>>>(b5, out);
}

// round 12
// speedup vs baseline: 2.0558x; 2.0558x over previous
#include <cuda_runtime.h>
#include <cuda_fp16.h>
#include <cstdint>

#define Q     65536
#define HH    256
#define WW    256
#define NPIX  (HH*WW)    /* 65536 */
#define MROWS (4*Q)      /* 262144 */
#define KC    288        /* conv GEMM K: 9 stages of 32 */
#define NHID  256

typedef unsigned int u32;

// ---------------- scratch (device globals; no allocation allowed) ----------
__device__ __half g_XCh[(size_t)NPIX * KC];
__device__ __half g_XCl[(size_t)NPIX * KC];
__device__ float  g_G  [(size_t)NPIX * NHID];
__device__ __half g_HAh[(size_t)MROWS * NHID];
__device__ __half g_HAl[(size_t)MROWS * NHID];
__device__ __half g_HBh[(size_t)MROWS * NHID];
__device__ __half g_HBl[(size_t)MROWS * NHID];
__device__ float g_PRED[(size_t)MROWS * 3];
__device__ float g_AREA[MROWS];
__device__ int    g_RIP[MROWS];
__device__ float4 g_RIV[MROWS];
__device__ __half g_W1[256 * KC];
__device__ __half g_W2[256 * 256];
__device__ __half g_W3[256 * 256];
__device__ __half g_W4[256 * 256];

// ---------------- helpers ---------------------------------------------------
__device__ __forceinline__ u32 pack2h(float x, float y) {
    __half2 t = __floats2half2_rn(x, y);
    return *reinterpret_cast<u32*>(&t);
}
__device__ __forceinline__ void mma_f16(float* d, const u32* a, const u32* b) {
    asm("mma.sync.aligned.m16n8k16.row.col.f32.f16.f16.f32 "
        "{%0,%1,%2,%3}, {%4,%5,%6,%7}, {%8,%9}, {%0,%1,%2,%3};"
        : "+f"(d[0]), "+f"(d[1]), "+f"(d[2]), "+f"(d[3])
        : "r"(a[0]), "r"(a[1]), "r"(a[2]), "r"(a[3]), "r"(b[0]), "r"(b[1]));
}
__device__ __forceinline__ void ldsm4(u32* r, const __half* p) {
    u32 a = (u32)__cvta_generic_to_shared(p);
    asm volatile("ldmatrix.sync.aligned.m8n8.x4.shared.b16 {%0,%1,%2,%3}, [%4];"
                 : "=r"(r[0]), "=r"(r[1]), "=r"(r[2]), "=r"(r[3]) : "r"(a));
}
__device__ __forceinline__ void cp16(__half* s, const __half* g) {
    u32 sa = (u32)__cvta_generic_to_shared(s);
    asm volatile("cp.async.cg.shared.global [%0], [%1], 16;" :: "r"(sa), "l"(g));
}
__device__ __forceinline__ void cp_commit() {
    asm volatile("cp.async.commit_group;" ::: "memory");
}
template<int N> __device__ __forceinline__ void cp_wait() {
    asm volatile("cp.async.wait_group %0;" :: "n"(N) : "memory");
}

// ---------------- W prep: transpose -> single fp16 plane --------------------
__global__ void prep_all_kernel(const float* __restrict__ w1,
                                const float* __restrict__ w2,
                                const float* __restrict__ w3,
                                const float* __restrict__ w4) {
    int i = blockIdx.x * 256 + threadIdx.x;
    const int S1 = 256 * KC;
    const int S  = 256 * 256;
    const float* w;
    __half* dst;
    int Kpad, idx;
    if (i < S1)              { w = w1; dst = g_W1; Kpad = KC;  idx = i; }
    else if (i < S1 + S)     { w = w2; dst = g_W2; Kpad = 256; idx = i - S1; }
    else if (i < S1 + 2 * S) { w = w3; dst = g_W3; Kpad = 256; idx = i - S1 - S; }
    else if (i < S1 + 3 * S) { w = w4; dst = g_W4; Kpad = 256; idx = i - S1 - 2 * S; }
    else return;
    int n = idx / Kpad, k = idx - n * Kpad;
    dst[idx] = __float2half_rn(w[(size_t)k * 256 + n]);
}

// ---------------- im2col: per-pixel 3x3 reflect patch -> fp16 hi/lo --------
__global__ void im2col_kernel(const float* __restrict__ F) {
    const int p = blockIdx.x;
    const int t = threadIdx.x;         // 0..287
    const int y0 = p >> 8, x0 = p & 255;
    int c  = t / 9;
    int k  = t - c * 9;
    int di = k / 3, dj = k - di * 3;
    int y = y0 + di - 1;
    int x = x0 + dj - 1;
    y = (y < 0) ? -y : ((y >= HH) ? 2 * HH - 2 - y : y);
    x = (x < 0) ? -x : ((x >= WW) ? 2 * WW - 2 - x : x);
    float v = F[(size_t)c * NPIX + y * WW + x];
    __half h = __float2half_rn(v);
    g_XCh[(size_t)p * KC + t] = h;
    g_XCl[(size_t)p * KC + t] = __float2half_rn(v - __half2float(h));
}

// ---------------- rowinfo: per-(q,s) scalars, once -------------------------
__global__ __launch_bounds__(256)
void rowinfo_kernel(const float* __restrict__ loc,
                    const float* __restrict__ cell) {
    int i = blockIdx.x * 256 + threadIdx.x;
    int q = i & (Q - 1);
    int s = i >> 16;

    float l0 = loc[(size_t)q * 2 + 0];
    float l1 = loc[(size_t)q * 2 + 1];
    float sy = (s & 2) ? 1.f : -1.f;
    float sx = (s & 1) ? 1.f : -1.f;
    float ly = l0 + sy * (1.f / HH) + 1e-6f;
    float lx = l1 + sx * (1.f / WW) + 1e-6f;
    ly = fminf(fmaxf(ly, -1.f + 1e-6f), 1.f - 1e-6f);
    lx = fminf(fmaxf(lx, -1.f + 1e-6f), 1.f - 1e-6f);
    int iy = (int)rintf(((ly + 1.f) * HH - 1.f) * 0.5f);
    int ix = (int)rintf(((lx + 1.f) * WW - 1.f) * 0.5f);
    iy = min(max(iy, 0), HH - 1);
    ix = min(max(ix, 0), WW - 1);
    float qy = -1.f + (2.f * iy + 1.f) / HH;
    float qx = -1.f + (2.f * ix + 1.f) / WW;
    float rel0 = (l0 - qy) * HH;
    float rel1 = (l1 - qx) * WW;
    float c0 = cell[(size_t)q * 2 + 0] * HH;
    float c1 = cell[(size_t)q * 2 + 1] * WW;

    g_RIP[i]  = iy * WW + ix;
    g_RIV[i]  = make_float4(rel0, rel1, c0, c1);
    g_AREA[i] = fabsf(rel0 * rel1) + 1e-9f;
}

// ---------------- combine2: H1 = relu(G[p] + rank-4 + b1) -> fp16 hi/lo ----
__global__ __launch_bounds__(256)
void combine2_kernel(const float* __restrict__ w1,
                     const float* __restrict__ b1,
                     __half* __restrict__ Hh,
                     __half* __restrict__ Hl) {
    __shared__ float sw[5 * 256];
    const int tid = threadIdx.x;
    for (int i = tid; i < 1024; i += 256) sw[i] = w1[288 * 256 + i];
    if (tid < 256) sw[1024 + tid] = b1[tid];
    __syncthreads();

    const size_t row = (size_t)blockIdx.x * 4 + (tid >> 6);
    const int c4 = (tid & 63) * 4;

    const int p = g_RIP[row];
    const float4 rc = g_RIV[row];

    float4 g  = *reinterpret_cast<const float4*>(g_G + (size_t)p * NHID + c4);
    float4 wA = *reinterpret_cast<const float4*>(sw + c4);
    float4 wB = *reinterpret_cast<const float4*>(sw + 256 + c4);
    float4 wC = *reinterpret_cast<const float4*>(sw + 512 + c4);
    float4 wD = *reinterpret_cast<const float4*>(sw + 768 + c4);
    float4 bb = *reinterpret_cast<const float4*>(sw + 1024 + c4);

    float v[4];
    v[0] = fmaxf(g.x + rc.x * wA.x + rc.y * wB.x + rc.z * wC.x + rc.w * wD.x + bb.x, 0.f);
    v[1] = fmaxf(g.y + rc.x * wA.y + rc.y * wB.y + rc.z * wC.y + rc.w * wD.y + bb.y, 0.f);
    v[2] = fmaxf(g.z + rc.x * wA.z + rc.y * wB.z + rc.z * wC.z + rc.w * wD.z + bb.z, 0.f);
    v[3] = fmaxf(g.w + rc.x * wA.w + rc.y * wB.w + rc.z * wC.w + rc.w * wD.w + bb.w, 0.f);

    float h[4];
#pragma unroll
    for (int j = 0; j < 4; ++j) h[j] = __half2float(__float2half_rn(v[j]));

    size_t off = row * NHID + c4;
    *reinterpret_cast<uint2*>(Hh + off) = make_uint2(pack2h(h[0], h[1]), pack2h(h[2], h[3]));
    *reinterpret_cast<uint2*>(Hl + off) = make_uint2(pack2h(v[0] - h[0], v[1] - h[1]),
                                                     pack2h(v[2] - h[2], v[3] - h[3]));
}

// ---------------- HMMA fp16-2x GEMM, 128x128 tile, 2 CTAs/SM ---------------
#define SST    40
#define PLANE  (128 * SST)
#define STAGE  (3 * PLANE)     /* Ah, Al, B */
#define SMEMB  (2 * STAGE * 2) /* 61440 B */

template<int K>
__device__ __forceinline__ void load_stage(
        __half* st,
        const __half* __restrict__ Ah, const __half* __restrict__ Al,
        const __half* __restrict__ B,
        int m0, int n0, int kb, int tid) {
#pragma unroll
    for (int i = 0; i < 2; ++i) {
        int chunk = tid + i * 256;
        int row = chunk >> 2;
        int c8  = (chunk & 3) << 3;
        size_t ga = (size_t)(m0 + row) * K + kb + c8;
        size_t gb = (size_t)(n0 + row) * K + kb + c8;
        int so = row * SST + c8;
        cp16(st + so,             Ah + ga);
        cp16(st + PLANE + so,     Al + ga);
        cp16(st + 2 * PLANE + so, B + gb);
    }
}

// MODE: 0 = fp32 raw out; 1 = bias+relu -> fp16 hi/lo; 2 = bias+relu -> dot w5 -> atomicAdd
template<int K, int MODE>
__global__ __launch_bounds__(256, 2)
void hmma_gemm(const __half* __restrict__ Ah,
               const __half* __restrict__ Al,
               const __half* __restrict__ B,
               const float* __restrict__ bias,
               void* __restrict__ Cout,
               __half* __restrict__ Clo,
               const float* __restrict__ w5) {
    extern __shared__ __half smem[];

    const int tid  = threadIdx.x;
    const int lane = tid & 31;
    const int wid  = tid >> 5;
    const int wm   = wid & 3;
    const int wn   = wid >> 2;
    const int m0   = blockIdx.y * 128;
    const int n0   = blockIdx.x * 128;
    const int lr   = lane >> 2;
    const int lq   = lane & 3;
    const int grp  = lane >> 3;
    const int rr   = lane & 7;

    const int a_row = wm * 32 + (grp & 1) * 8 + rr;
    const int a_kb  = (grp >> 1) * 8;
    const int b_row = wn * 64 + (grp >> 1) * 8 + rr;
    const int b_kb  = (grp & 1) * 8;

    float acc[2][8][4];
#pragma unroll
    for (int i = 0; i < 2; ++i)
#pragma unroll
        for (int j = 0; j < 8; ++j)
#pragma unroll
            for (int c = 0; c < 4; ++c) acc[i][j][c] = 0.f;

    constexpr int S = K / 32;
    load_stage<K>(smem, Ah, Al, B, m0, n0, 0, tid);
    cp_commit();

    for (int s = 0; s < S; ++s) {
        if (s + 1 < S) {
            load_stage<K>(smem + ((s + 1) & 1) * STAGE, Ah, Al, B,
                          m0, n0, (s + 1) * 32, tid);
            cp_commit();
            cp_wait<1>();
        } else {
            cp_wait<0>();
        }
        __syncthreads();

        const __half* sAh = smem + (s & 1) * STAGE;
        const __half* sAl = sAh + PLANE;
        const __half* sB  = sAh + 2 * PLANE;

#pragma unroll
        for (int ks = 0; ks < 32; ks += 16) {
            u32 af[2][2][4];
#pragma unroll
            for (int ti = 0; ti < 2; ++ti) {
                ldsm4(af[ti][0], sAh + (a_row + ti * 16) * SST + ks + a_kb);
                ldsm4(af[ti][1], sAl + (a_row + ti * 16) * SST + ks + a_kb);
            }
#pragma unroll
            for (int jp = 0; jp < 4; ++jp) {
                u32 bh[4];
                ldsm4(bh, sB + (b_row + jp * 16) * SST + ks + b_kb);
#pragma unroll
                for (int ti = 0; ti < 2; ++ti) {
                    mma_f16(acc[ti][2 * jp],     af[ti][0], bh);
                    mma_f16(acc[ti][2 * jp],     af[ti][1], bh);
                    mma_f16(acc[ti][2 * jp + 1], af[ti][0], bh + 2);
                    mma_f16(acc[ti][2 * jp + 1], af[ti][1], bh + 2);
                }
            }
        }
        __syncthreads();
    }

    // ---- epilogue ----
    if (MODE == 0) {
        float* C = (float*)Cout;
#pragma unroll
        for (int ti = 0; ti < 2; ++ti) {
            int row0 = m0 + wm * 32 + ti * 16 + lr;
#pragma unroll
            for (int tj = 0; tj < 8; ++tj) {
                int col0 = n0 + wn * 64 + tj * 8 + lq * 2;
#pragma unroll
                for (int half = 0; half < 2; ++half) {
                    size_t off = (size_t)(row0 + half * 8) * NHID + col0;
                    *reinterpret_cast<float2*>(C + off) =
                        make_float2(acc[ti][tj][half * 2 + 0],
                                    acc[ti][tj][half * 2 + 1]);
                }
            }
        }
    } else if (MODE == 1) {
        __half* Chi = (__half*)Cout;
#pragma unroll
        for (int ti = 0; ti < 2; ++ti) {
            int row0 = m0 + wm * 32 + ti * 16 + lr;
#pragma unroll
            for (int tj = 0; tj < 8; ++tj) {
                int col0 = n0 + wn * 64 + tj * 8 + lq * 2;
                float b0 = bias[col0], b1 = bias[col0 + 1];
#pragma unroll
                for (int half = 0; half < 2; ++half) {
                    size_t off = (size_t)(row0 + half * 8) * NHID + col0;
                    float v0 = fmaxf(acc[ti][tj][half * 2 + 0] + b0, 0.f);
                    float v1 = fmaxf(acc[ti][tj][half * 2 + 1] + b1, 0.f);
                    float h0 = __half2float(__float2half_rn(v0));
                    float h1 = __half2float(__float2half_rn(v1));
                    *reinterpret_cast<u32*>(Chi + off) = pack2h(h0, h1);
                    *reinterpret_cast<u32*>(Clo + off) = pack2h(v0 - h0, v1 - h1);
                }
            }
        }
    } else {
        float part[2][2][3];
#pragma unroll
        for (int ti = 0; ti < 2; ++ti)
#pragma unroll
            for (int h = 0; h < 2; ++h)
#pragma unroll
                for (int c = 0; c < 3; ++c) part[ti][h][c] = 0.f;

#pragma unroll
        for (int tj = 0; tj < 8; ++tj) {
            int col0 = n0 + wn * 64 + tj * 8 + lq * 2;
            float b0 = bias[col0], b1 = bias[col0 + 1];
            float w50[3], w51[3];
#pragma unroll
            for (int c = 0; c < 3; ++c) {
                w50[c] = w5[col0 * 3 + c];
                w51[c] = w5[(col0 + 1) * 3 + c];
            }
#pragma unroll
            for (int ti = 0; ti < 2; ++ti)
#pragma unroll
                for (int half = 0; half < 2; ++half) {
                    float v0 = fmaxf(acc[ti][tj][half * 2 + 0] + b0, 0.f);
                    float v1 = fmaxf(acc[ti][tj][half * 2 + 1] + b1, 0.f);
#pragma unroll
                    for (int c = 0; c < 3; ++c)
                        part[ti][half][c] += v0 * w50[c] + v1 * w51[c];
                }
        }
#pragma unroll
        for (int ti = 0; ti < 2; ++ti)
#pragma unroll
            for (int h = 0; h < 2; ++h)
#pragma unroll
                for (int c = 0; c < 3; ++c) {
                    float v = part[ti][h][c];
                    v += __shfl_xor_sync(0xffffffffu, v, 1);
                    v += __shfl_xor_sync(0xffffffffu, v, 2);
                    part[ti][h][c] = v;
                }
        float* sp = reinterpret_cast<float*>(smem);
        if (lq == 0) {
#pragma unroll
            for (int ti = 0; ti < 2; ++ti)
#pragma unroll
                for (int h = 0; h < 2; ++h) {
                    int row = wm * 32 + ti * 16 + h * 8 + lr;
#pragma unroll
                    for (int c = 0; c < 3; ++c)
                        sp[(wn * 128 + row) * 3 + c] = part[ti][h][c];
                }
        }
        __syncthreads();
        for (int i = tid; i < 384; i += 256) {
            float v = sp[i] + sp[384 + i];
            atomicAdd(&g_PRED[(size_t)(m0 + i / 3) * 3 + (i % 3)], v);
        }
    }
}

// ---------------- output combine --------------------------------------------
__global__ __launch_bounds__(256)
void out_combine(const float* __restrict__ b5, float* __restrict__ out) {
    int q = blockIdx.x * 256 + threadIdx.x;
    float ar[4], tot = 0.f;
#pragma unroll
    for (int s = 0; s < 4; ++s) { ar[s] = g_AREA[(size_t)s * Q + q]; tot += ar[s]; }
    float r0 = 0.f, r1 = 0.f, r2 = 0.f;
#pragma unroll
    for (int s = 0; s < 4; ++s) {
        float wgt = ar[3 - s] / tot;
        size_t base = ((size_t)s * Q + q) * 3;
        r0 += (g_PRED[base + 0] + b5[0]) * wgt;
        r1 += (g_PRED[base + 1] + b5[1]) * wgt;
        r2 += (g_PRED[base + 2] + b5[2]) * wgt;
    }
    out[(size_t)q * 3 + 0] = r0;
    out[(size_t)q * 3 + 1] = r1;
    out[(size_t)q * 3 + 2] = r2;
}

// ---------------- launch ----------------------------------------------------
extern "C" void kernel_launch(void* const* d_in, const int* in_sizes, int n_in,
                              void* d_out, int out_size) {
    const float* F    = (const float*)d_in[0];
    const float* loc  = (const float*)d_in[1];
    const float* cell = (const float*)d_in[2];
    const float* w1 = (const float*)d_in[3];
    const float* b1 = (const float*)d_in[4];
    const float* w2 = (const float*)d_in[5];
    const float* b2 = (const float*)d_in[6];
    const float* w3 = (const float*)d_in[7];
    const float* b3 = (const float*)d_in[8];
    const float* w4 = (const float*)d_in[9];
    const float* b4 = (const float*)d_in[10];
    const float* w5 = (const float*)d_in[11];
    const float* b5 = (const float*)d_in[12];
    float* out = (float*)d_out;

    __half *XCh, *XCl, *HAh, *HAl, *HBh, *HBl;
    __half *W1, *W2, *W3, *W4;
    float *G, *PRED;
    cudaGetSymbolAddress((void**)&XCh, g_XCh); cudaGetSymbolAddress((void**)&XCl, g_XCl);
    cudaGetSymbolAddress((void**)&G,   g_G);
    cudaGetSymbolAddress((void**)&PRED, g_PRED);
    cudaGetSymbolAddress((void**)&HAh, g_HAh); cudaGetSymbolAddress((void**)&HAl, g_HAl);
    cudaGetSymbolAddress((void**)&HBh, g_HBh); cudaGetSymbolAddress((void**)&HBl, g_HBl);
    cudaGetSymbolAddress((void**)&W1, g_W1);
    cudaGetSymbolAddress((void**)&W2, g_W2);
    cudaGetSymbolAddress((void**)&W3, g_W3);
    cudaGetSymbolAddress((void**)&W4, g_W4);

    cudaFuncSetAttribute(hmma_gemm<KC, 0>,
        cudaFuncAttributeMaxDynamicSharedMemorySize, SMEMB);
    cudaFuncSetAttribute(hmma_gemm<256, 1>,
        cudaFuncAttributeMaxDynamicSharedMemorySize, SMEMB);
    cudaFuncSetAttribute(hmma_gemm<256, 2>,
        cudaFuncAttributeMaxDynamicSharedMemorySize, SMEMB);

    cudaMemsetAsync(PRED, 0, (size_t)MROWS * 3 * sizeof(float));

    const int PREP_ELEMS = 256 * KC + 3 * 256 * 256;
    prep_all_kernel<<<(PREP_ELEMS + 255) / 256, 256>>>(w1, w2, w3, w4);

    im2col_kernel<<<NPIX, KC>>>(F);
    rowinfo_kernel<<<MROWS / 256, 256>>>(loc, cell);

    // conv GEMM: G[65536,256] = XC @ W1[0:288]^T
    hmma_gemm<KC, 0><<<dim3(2, NPIX / 128), 256, SMEMB>>>(
        XCh, XCl, W1, nullptr, G, nullptr, nullptr);

    combine2_kernel<<<MROWS / 4, 256>>>(w1, b1, HAh, HAl);

    dim3 ggrid(2, MROWS / 128);
    hmma_gemm<256, 1><<<ggrid, 256, SMEMB>>>(HAh, HAl, W2, b2, HBh, HBl, nullptr);
    hmma_gemm<256, 1><<<ggrid, 256, SMEMB>>>(HBh, HBl, W3, b3, HAh, HAl, nullptr);
    hmma_gemm<256, 2><<<ggrid, 256, SMEMB>>>(HAh, HAl, W4, b4, nullptr, nullptr, w5);

    out_combine<<<Q / 256, 256>>>(b5, out);
}

// round 13
// speedup vs baseline: 2.1663x; 1.0537x over previous
#include <cuda_runtime.h>
#include <cuda_fp16.h>
#include <cstdint>

#define Q     65536
#define HH    256
#define WW    256
#define NPIX  (HH*WW)    /* 65536 */
#define MROWS (4*Q)      /* 262144 */
#define KC    288
#define NHID  256

typedef unsigned int u32;

// ---------------- scratch (device globals; no allocation allowed) ----------
__device__ __half g_XCh[(size_t)NPIX * KC];
__device__ __half g_XCl[(size_t)NPIX * KC];
__device__ float  g_G  [(size_t)NPIX * NHID];
__device__ __half g_HAh[(size_t)MROWS * NHID];
__device__ __half g_HAl[(size_t)MROWS * NHID];
__device__ __half g_HBh[(size_t)MROWS * NHID];
__device__ __half g_HBl[(size_t)MROWS * NHID];
__device__ float g_PRED[(size_t)MROWS * 3];
__device__ float g_AREA[MROWS];
__device__ int    g_RIP[MROWS];
__device__ float4 g_RIV[MROWS];
__device__ __half g_W1[256 * KC];
__device__ __half g_W2[256 * 256];
__device__ __half g_W3[256 * 256];
__device__ __half g_W4[256 * 256];

// ---------------- helpers ---------------------------------------------------
__device__ __forceinline__ u32 pack2h(float x, float y) {
    __half2 t = __floats2half2_rn(x, y);
    return *reinterpret_cast<u32*>(&t);
}
__device__ __forceinline__ void mma_f16(float* d, const u32* a, const u32* b) {
    asm("mma.sync.aligned.m16n8k16.row.col.f32.f16.f16.f32 "
        "{%0,%1,%2,%3}, {%4,%5,%6,%7}, {%8,%9}, {%0,%1,%2,%3};"
        : "+f"(d[0]), "+f"(d[1]), "+f"(d[2]), "+f"(d[3])
        : "r"(a[0]), "r"(a[1]), "r"(a[2]), "r"(a[3]), "r"(b[0]), "r"(b[1]));
}
__device__ __forceinline__ void ldsm4(u32* r, const __half* p) {
    u32 a = (u32)__cvta_generic_to_shared(p);
    asm volatile("ldmatrix.sync.aligned.m8n8.x4.shared.b16 {%0,%1,%2,%3}, [%4];"
                 : "=r"(r[0]), "=r"(r[1]), "=r"(r[2]), "=r"(r[3]) : "r"(a));
}
__device__ __forceinline__ void cp16(__half* s, const __half* g) {
    u32 sa = (u32)__cvta_generic_to_shared(s);
    asm volatile("cp.async.cg.shared.global [%0], [%1], 16;" :: "r"(sa), "l"(g));
}
__device__ __forceinline__ void cp_commit() {
    asm volatile("cp.async.commit_group;" ::: "memory");
}
template<int N> __device__ __forceinline__ void cp_wait() {
    asm volatile("cp.async.wait_group %0;" :: "n"(N) : "memory");
}

// ---------------- W prep: transpose -> single fp16 plane --------------------
__global__ void prep_all_kernel(const float* __restrict__ w1,
                                const float* __restrict__ w2,
                                const float* __restrict__ w3,
                                const float* __restrict__ w4) {
    int i = blockIdx.x * 256 + threadIdx.x;
    const int S1 = 256 * KC;
    const int S  = 256 * 256;
    const float* w;
    __half* dst;
    int Kpad, idx;
    if (i < S1)              { w = w1; dst = g_W1; Kpad = KC;  idx = i; }
    else if (i < S1 + S)     { w = w2; dst = g_W2; Kpad = 256; idx = i - S1; }
    else if (i < S1 + 2 * S) { w = w3; dst = g_W3; Kpad = 256; idx = i - S1 - S; }
    else if (i < S1 + 3 * S) { w = w4; dst = g_W4; Kpad = 256; idx = i - S1 - 2 * S; }
    else return;
    int n = idx / Kpad, k = idx - n * Kpad;
    dst[idx] = __float2half_rn(w[(size_t)k * 256 + n]);
}

// ---------------- im2col: per-pixel 3x3 reflect patch -> fp16 hi/lo --------
__global__ void im2col_kernel(const float* __restrict__ F) {
    const int p = blockIdx.x;
    const int t = threadIdx.x;         // 0..287
    const int y0 = p >> 8, x0 = p & 255;
    int c  = t / 9;
    int k  = t - c * 9;
    int di = k / 3, dj = k - di * 3;
    int y = y0 + di - 1;
    int x = x0 + dj - 1;
    y = (y < 0) ? -y : ((y >= HH) ? 2 * HH - 2 - y : y);
    x = (x < 0) ? -x : ((x >= WW) ? 2 * WW - 2 - x : x);
    float v = F[(size_t)c * NPIX + y * WW + x];
    __half h = __float2half_rn(v);
    g_XCh[(size_t)p * KC + t] = h;
    g_XCl[(size_t)p * KC + t] = __float2half_rn(v - __half2float(h));
}

// ---------------- rowinfo ----------------------------------------------------
__global__ __launch_bounds__(256)
void rowinfo_kernel(const float* __restrict__ loc,
                    const float* __restrict__ cell) {
    int i = blockIdx.x * 256 + threadIdx.x;
    int q = i & (Q - 1);
    int s = i >> 16;

    float l0 = loc[(size_t)q * 2 + 0];
    float l1 = loc[(size_t)q * 2 + 1];
    float sy = (s & 2) ? 1.f : -1.f;
    float sx = (s & 1) ? 1.f : -1.f;
    float ly = l0 + sy * (1.f / HH) + 1e-6f;
    float lx = l1 + sx * (1.f / WW) + 1e-6f;
    ly = fminf(fmaxf(ly, -1.f + 1e-6f), 1.f - 1e-6f);
    lx = fminf(fmaxf(lx, -1.f + 1e-6f), 1.f - 1e-6f);
    int iy = (int)rintf(((ly + 1.f) * HH - 1.f) * 0.5f);
    int ix = (int)rintf(((lx + 1.f) * WW - 1.f) * 0.5f);
    iy = min(max(iy, 0), HH - 1);
    ix = min(max(ix, 0), WW - 1);
    float qy = -1.f + (2.f * iy + 1.f) / HH;
    float qx = -1.f + (2.f * ix + 1.f) / WW;
    float rel0 = (l0 - qy) * HH;
    float rel1 = (l1 - qx) * WW;
    float c0 = cell[(size_t)q * 2 + 0] * HH;
    float c1 = cell[(size_t)q * 2 + 1] * WW;

    g_RIP[i]  = iy * WW + ix;
    g_RIV[i]  = make_float4(rel0, rel1, c0, c1);
    g_AREA[i] = fabsf(rel0 * rel1) + 1e-9f;
}

// ---------------- combine2 ---------------------------------------------------
__global__ __launch_bounds__(256)
void combine2_kernel(const float* __restrict__ w1,
                     const float* __restrict__ b1,
                     __half* __restrict__ Hh,
                     __half* __restrict__ Hl) {
    __shared__ float sw[5 * 256];
    const int tid = threadIdx.x;
    for (int i = tid; i < 1024; i += 256) sw[i] = w1[288 * 256 + i];
    if (tid < 256) sw[1024 + tid] = b1[tid];
    __syncthreads();

    const size_t row = (size_t)blockIdx.x * 4 + (tid >> 6);
    const int c4 = (tid & 63) * 4;

    const int p = g_RIP[row];
    const float4 rc = g_RIV[row];

    float4 g  = *reinterpret_cast<const float4*>(g_G + (size_t)p * NHID + c4);
    float4 wA = *reinterpret_cast<const float4*>(sw + c4);
    float4 wB = *reinterpret_cast<const float4*>(sw + 256 + c4);
    float4 wC = *reinterpret_cast<const float4*>(sw + 512 + c4);
    float4 wD = *reinterpret_cast<const float4*>(sw + 768 + c4);
    float4 bb = *reinterpret_cast<const float4*>(sw + 1024 + c4);

    float v[4];
    v[0] = fmaxf(g.x + rc.x * wA.x + rc.y * wB.x + rc.z * wC.x + rc.w * wD.x + bb.x, 0.f);
    v[1] = fmaxf(g.y + rc.x * wA.y + rc.y * wB.y + rc.z * wC.y + rc.w * wD.y + bb.y, 0.f);
    v[2] = fmaxf(g.z + rc.x * wA.z + rc.y * wB.z + rc.z * wC.z + rc.w * wD.z + bb.z, 0.f);
    v[3] = fmaxf(g.w + rc.x * wA.w + rc.y * wB.w + rc.z * wC.w + rc.w * wD.w + bb.w, 0.f);

    float h[4];
#pragma unroll
    for (int j = 0; j < 4; ++j) h[j] = __half2float(__float2half_rn(v[j]));

    size_t off = row * NHID + c4;
    *reinterpret_cast<uint2*>(Hh + off) = make_uint2(pack2h(h[0], h[1]), pack2h(h[2], h[3]));
    *reinterpret_cast<uint2*>(Hl + off) = make_uint2(pack2h(v[0] - h[0], v[1] - h[1]),
                                                     pack2h(v[2] - h[2], v[3] - h[3]));
}

// ---------------- HMMA fp16-2x GEMM, 128x128 tile, templated BK ------------
// SST = BK + 8 (halfs); planes: Ah, Al, B

template<int K, int BK>
__device__ __forceinline__ void load_stage(
        __half* st,
        const __half* __restrict__ Ah, const __half* __restrict__ Al,
        const __half* __restrict__ B,
        int m0, int n0, int kb, int tid) {
    constexpr int SSTl   = BK + 8;
    constexpr int PLANEl = 128 * SSTl;
    constexpr int CPR    = BK / 8;              // 16B chunks per row
    constexpr int ITERS  = 128 * CPR / 256;     // per-thread chunks
#pragma unroll
    for (int i = 0; i < ITERS; ++i) {
        int chunk = tid + i * 256;
        int row = chunk / CPR;
        int c8  = (chunk % CPR) * 8;
        size_t ga = (size_t)(m0 + row) * K + kb + c8;
        size_t gb = (size_t)(n0 + row) * K + kb + c8;
        int so = row * SSTl + c8;
        cp16(st + so,              Ah + ga);
        cp16(st + PLANEl + so,     Al + ga);
        cp16(st + 2 * PLANEl + so, B + gb);
    }
}

// MODE: 0 = fp32 raw out; 1 = bias+relu -> fp16 hi/lo; 2 = bias+relu -> dot w5 -> atomicAdd
template<int K, int BK, int MODE>
__global__ __launch_bounds__(256, 2)
void hmma_gemm(const __half* __restrict__ Ah,
               const __half* __restrict__ Al,
               const __half* __restrict__ B,
               const float* __restrict__ bias,
               void* __restrict__ Cout,
               __half* __restrict__ Clo,
               const float* __restrict__ w5) {
    extern __shared__ __half smem[];
    constexpr int SSTl   = BK + 8;
    constexpr int PLANEl = 128 * SSTl;
    constexpr int STAGEl = 3 * PLANEl;

    const int tid  = threadIdx.x;
    const int lane = tid & 31;
    const int wid  = tid >> 5;
    const int wm   = wid & 3;
    const int wn   = wid >> 2;
    const int m0   = blockIdx.y * 128;
    const int n0   = blockIdx.x * 128;
    const int lr   = lane >> 2;
    const int lq   = lane & 3;
    const int grp  = lane >> 3;
    const int rr   = lane & 7;

    const int a_row = wm * 32 + (grp & 1) * 8 + rr;
    const int a_kb  = (grp >> 1) * 8;
    const int b_row = wn * 64 + (grp >> 1) * 8 + rr;
    const int b_kb  = (grp & 1) * 8;

    float acc[2][8][4];
#pragma unroll
    for (int i = 0; i < 2; ++i)
#pragma unroll
        for (int j = 0; j < 8; ++j)
#pragma unroll
            for (int c = 0; c < 4; ++c) acc[i][j][c] = 0.f;

    constexpr int S = K / BK;
    load_stage<K, BK>(smem, Ah, Al, B, m0, n0, 0, tid);
    cp_commit();

    for (int s = 0; s < S; ++s) {
        if (s + 1 < S) {
            load_stage<K, BK>(smem + ((s + 1) & 1) * STAGEl, Ah, Al, B,
                              m0, n0, (s + 1) * BK, tid);
            cp_commit();
            cp_wait<1>();
        } else {
            cp_wait<0>();
        }
        __syncthreads();

        const __half* sAh = smem + (s & 1) * STAGEl;
        const __half* sAl = sAh + PLANEl;
        const __half* sB  = sAh + 2 * PLANEl;

#pragma unroll
        for (int ks = 0; ks < BK; ks += 16) {
            u32 af[2][2][4];
#pragma unroll
            for (int ti = 0; ti < 2; ++ti) {
                ldsm4(af[ti][0], sAh + (a_row + ti * 16) * SSTl + ks + a_kb);
                ldsm4(af[ti][1], sAl + (a_row + ti * 16) * SSTl + ks + a_kb);
            }
#pragma unroll
            for (int jp = 0; jp < 4; ++jp) {
                u32 bh[4];
                ldsm4(bh, sB + (b_row + jp * 16) * SSTl + ks + b_kb);
                // af0 products first, then af1: RAW distance 4 per accumulator
#pragma unroll
                for (int ti = 0; ti < 2; ++ti) {
                    mma_f16(acc[ti][2 * jp],     af[ti][0], bh);
                    mma_f16(acc[ti][2 * jp + 1], af[ti][0], bh + 2);
                }
#pragma unroll
                for (int ti = 0; ti < 2; ++ti) {
                    mma_f16(acc[ti][2 * jp],     af[ti][1], bh);
                    mma_f16(acc[ti][2 * jp + 1], af[ti][1], bh + 2);
                }
            }
        }
        __syncthreads();
    }

    // ---- epilogue ----
    if (MODE == 0) {
        float* C = (float*)Cout;
#pragma unroll
        for (int ti = 0; ti < 2; ++ti) {
            int row0 = m0 + wm * 32 + ti * 16 + lr;
#pragma unroll
            for (int tj = 0; tj < 8; ++tj) {
                int col0 = n0 + wn * 64 + tj * 8 + lq * 2;
#pragma unroll
                for (int half = 0; half < 2; ++half) {
                    size_t off = (size_t)(row0 + half * 8) * NHID + col0;
                    *reinterpret_cast<float2*>(C + off) =
                        make_float2(acc[ti][tj][half * 2 + 0],
                                    acc[ti][tj][half * 2 + 1]);
                }
            }
        }
    } else if (MODE == 1) {
        __half* Chi = (__half*)Cout;
#pragma unroll
        for (int ti = 0; ti < 2; ++ti) {
            int row0 = m0 + wm * 32 + ti * 16 + lr;
#pragma unroll
            for (int tj = 0; tj < 8; ++tj) {
                int col0 = n0 + wn * 64 + tj * 8 + lq * 2;
                float b0 = bias[col0], b1 = bias[col0 + 1];
#pragma unroll
                for (int half = 0; half < 2; ++half) {
                    size_t off = (size_t)(row0 + half * 8) * NHID + col0;
                    float v0 = fmaxf(acc[ti][tj][half * 2 + 0] + b0, 0.f);
                    float v1 = fmaxf(acc[ti][tj][half * 2 + 1] + b1, 0.f);
                    float h0 = __half2float(__float2half_rn(v0));
                    float h1 = __half2float(__float2half_rn(v1));
                    *reinterpret_cast<u32*>(Chi + off) = pack2h(h0, h1);
                    *reinterpret_cast<u32*>(Clo + off) = pack2h(v0 - h0, v1 - h1);
                }
            }
        }
    } else {
        float part[2][2][3];
#pragma unroll
        for (int ti = 0; ti < 2; ++ti)
#pragma unroll
            for (int h = 0; h < 2; ++h)
#pragma unroll
                for (int c = 0; c < 3; ++c) part[ti][h][c] = 0.f;

#pragma unroll
        for (int tj = 0; tj < 8; ++tj) {
            int col0 = n0 + wn * 64 + tj * 8 + lq * 2;
            float b0 = bias[col0], b1 = bias[col0 + 1];
            float w50[3], w51[3];
#pragma unroll
            for (int c = 0; c < 3; ++c) {
                w50[c] = w5[col0 * 3 + c];
                w51[c] = w5[(col0 + 1) * 3 + c];
            }
#pragma unroll
            for (int ti = 0; ti < 2; ++ti)
#pragma unroll
                for (int half = 0; half < 2; ++half) {
                    float v0 = fmaxf(acc[ti][tj][half * 2 + 0] + b0, 0.f);
                    float v1 = fmaxf(acc[ti][tj][half * 2 + 1] + b1, 0.f);
#pragma unroll
                    for (int c = 0; c < 3; ++c)
                        part[ti][half][c] += v0 * w50[c] + v1 * w51[c];
                }
        }
#pragma unroll
        for (int ti = 0; ti < 2; ++ti)
#pragma unroll
            for (int h = 0; h < 2; ++h)
#pragma unroll
                for (int c = 0; c < 3; ++c) {
                    float v = part[ti][h][c];
                    v += __shfl_xor_sync(0xffffffffu, v, 1);
                    v += __shfl_xor_sync(0xffffffffu, v, 2);
                    part[ti][h][c] = v;
                }
        float* sp = reinterpret_cast<float*>(smem);
        if (lq == 0) {
#pragma unroll
            for (int ti = 0; ti < 2; ++ti)
#pragma unroll
                for (int h = 0; h < 2; ++h) {
                    int row = wm * 32 + ti * 16 + h * 8 + lr;
#pragma unroll
                    for (int c = 0; c < 3; ++c)
                        sp[(wn * 128 + row) * 3 + c] = part[ti][h][c];
                }
        }
        __syncthreads();
        for (int i = tid; i < 384; i += 256) {
            float v = sp[i] + sp[384 + i];
            atomicAdd(&g_PRED[(size_t)(m0 + i / 3) * 3 + (i % 3)], v);
        }
    }
}

// ---------------- output combine --------------------------------------------
__global__ __launch_bounds__(256)
void out_combine(const float* __restrict__ b5, float* __restrict__ out) {
    int q = blockIdx.x * 256 + threadIdx.x;
    float ar[4], tot = 0.f;
#pragma unroll
    for (int s = 0; s < 4; ++s) { ar[s] = g_AREA[(size_t)s * Q + q]; tot += ar[s]; }
    float r0 = 0.f, r1 = 0.f, r2 = 0.f;
#pragma unroll
    for (int s = 0; s < 4; ++s) {
        float wgt = ar[3 - s] / tot;
        size_t base = ((size_t)s * Q + q) * 3;
        r0 += (g_PRED[base + 0] + b5[0]) * wgt;
        r1 += (g_PRED[base + 1] + b5[1]) * wgt;
        r2 += (g_PRED[base + 2] + b5[2]) * wgt;
    }
    out[(size_t)q * 3 + 0] = r0;
    out[(size_t)q * 3 + 1] = r1;
    out[(size_t)q * 3 + 2] = r2;
}

// ---------------- launch ----------------------------------------------------
#define SMEMB32 (2 * 3 * 128 * 40 * 2)   /* 61440  */
#define SMEMB64 (2 * 3 * 128 * 72 * 2)   /* 110592 */

extern "C" void kernel_launch(void* const* d_in, const int* in_sizes, int n_in,
                              void* d_out, int out_size) {
    const float* F    = (const float*)d_in[0];
    const float* loc  = (const float*)d_in[1];
    const float* cell = (const float*)d_in[2];
    const float* w1 = (const float*)d_in[3];
    const float* b1 = (const float*)d_in[4];
    const float* w2 = (const float*)d_in[5];
    const float* b2 = (const float*)d_in[6];
    const float* w3 = (const float*)d_in[7];
    const float* b3 = (const float*)d_in[8];
    const float* w4 = (const float*)d_in[9];
    const float* b4 = (const float*)d_in[10];
    const float* w5 = (const float*)d_in[11];
    const float* b5 = (const float*)d_in[12];
    float* out = (float*)d_out;

    __half *XCh, *XCl, *HAh, *HAl, *HBh, *HBl;
    __half *W1, *W2, *W3, *W4;
    float *G, *PRED;
    cudaGetSymbolAddress((void**)&XCh, g_XCh); cudaGetSymbolAddress((void**)&XCl, g_XCl);
    cudaGetSymbolAddress((void**)&G,   g_G);
    cudaGetSymbolAddress((void**)&PRED, g_PRED);
    cudaGetSymbolAddress((void**)&HAh, g_HAh); cudaGetSymbolAddress((void**)&HAl, g_HAl);
    cudaGetSymbolAddress((void**)&HBh, g_HBh); cudaGetSymbolAddress((void**)&HBl, g_HBl);
    cudaGetSymbolAddress((void**)&W1, g_W1);
    cudaGetSymbolAddress((void**)&W2, g_W2);
    cudaGetSymbolAddress((void**)&W3, g_W3);
    cudaGetSymbolAddress((void**)&W4, g_W4);

    cudaFuncSetAttribute(hmma_gemm<KC, 32, 0>,
        cudaFuncAttributeMaxDynamicSharedMemorySize, SMEMB32);
    cudaFuncSetAttribute(hmma_gemm<256, 64, 1>,
        cudaFuncAttributeMaxDynamicSharedMemorySize, SMEMB64);
    cudaFuncSetAttribute(hmma_gemm<256, 64, 2>,
        cudaFuncAttributeMaxDynamicSharedMemorySize, SMEMB64);

    cudaMemsetAsync(PRED, 0, (size_t)MROWS * 3 * sizeof(float));

    const int PREP_ELEMS = 256 * KC + 3 * 256 * 256;
    prep_all_kernel<<<(PREP_ELEMS + 255) / 256, 256>>>(w1, w2, w3, w4);

    im2col_kernel<<<NPIX, KC>>>(F);
    rowinfo_kernel<<<MROWS / 256, 256>>>(loc, cell);

    // conv GEMM: G[65536,256] = XC @ W1[0:288]^T
    hmma_gemm<KC, 32, 0><<<dim3(2, NPIX / 128), 256, SMEMB32>>>(
        XCh, XCl, W1, nullptr, G, nullptr, nullptr);

    combine2_kernel<<<MROWS / 4, 256>>>(w1, b1, HAh, HAl);

    dim3 ggrid(2, MROWS / 128);
    hmma_gemm<256, 64, 1><<<ggrid, 256, SMEMB64>>>(HAh, HAl, W2, b2, HBh, HBl, nullptr);
    hmma_gemm<256, 64, 1><<<ggrid, 256, SMEMB64>>>(HBh, HBl, W3, b3, HAh, HAl, nullptr);
    hmma_gemm<256, 64, 2><<<ggrid, 256, SMEMB64>>>(HAh, HAl, W4, b4, nullptr, nullptr, w5);

    out_combine<<<Q / 256, 256>>>(b5, out);
}

// round 14
// speedup vs baseline: 3.3041x; 1.5252x over previous
#include <cuda_runtime.h>
#include <cuda_fp16.h>
#include <cstdint>

#define Q     65536
#define HH    256
#define WW    256
#define NPIX  (HH*WW)    /* 65536 */
#define MROWS (4*Q)      /* 262144 */
#define KC    288
#define NHID  256

typedef unsigned int u32;

// ---------------- scratch (device globals; no allocation allowed) ----------
__device__ __half g_XCh[(size_t)NPIX * KC];
__device__ __half g_XCl[(size_t)NPIX * KC];
__device__ float  g_G  [(size_t)NPIX * NHID];
__device__ __half g_HA [(size_t)MROWS * NHID];
__device__ __half g_HB [(size_t)MROWS * NHID];
__device__ float g_PRED[(size_t)MROWS * 3];
__device__ float g_AREA[MROWS];
__device__ int    g_RIP[MROWS];
__device__ float4 g_RIV[MROWS];
__device__ __half g_W1[256 * KC];
__device__ __half g_W2[256 * 256];
__device__ __half g_W3[256 * 256];
__device__ __half g_W4[256 * 256];

// ---------------- helpers ---------------------------------------------------
__device__ __forceinline__ u32 pack2h(float x, float y) {
    __half2 t = __floats2half2_rn(x, y);
    return *reinterpret_cast<u32*>(&t);
}
__device__ __forceinline__ void mma_f16(float* d, const u32* a, const u32* b) {
    asm("mma.sync.aligned.m16n8k16.row.col.f32.f16.f16.f32 "
        "{%0,%1,%2,%3}, {%4,%5,%6,%7}, {%8,%9}, {%0,%1,%2,%3};"
        : "+f"(d[0]), "+f"(d[1]), "+f"(d[2]), "+f"(d[3])
        : "r"(a[0]), "r"(a[1]), "r"(a[2]), "r"(a[3]), "r"(b[0]), "r"(b[1]));
}
__device__ __forceinline__ void ldsm4(u32* r, const __half* p) {
    u32 a = (u32)__cvta_generic_to_shared(p);
    asm volatile("ldmatrix.sync.aligned.m8n8.x4.shared.b16 {%0,%1,%2,%3}, [%4];"
                 : "=r"(r[0]), "=r"(r[1]), "=r"(r[2]), "=r"(r[3]) : "r"(a));
}
__device__ __forceinline__ void cp16(__half* s, const __half* g) {
    u32 sa = (u32)__cvta_generic_to_shared(s);
    asm volatile("cp.async.cg.shared.global [%0], [%1], 16;" :: "r"(sa), "l"(g));
}
__device__ __forceinline__ void cp_commit() {
    asm volatile("cp.async.commit_group;" ::: "memory");
}
template<int N> __device__ __forceinline__ void cp_wait() {
    asm volatile("cp.async.wait_group %0;" :: "n"(N) : "memory");
}

// ---------------- W prep: transpose -> single fp16 plane --------------------
__global__ void prep_all_kernel(const float* __restrict__ w1,
                                const float* __restrict__ w2,
                                const float* __restrict__ w3,
                                const float* __restrict__ w4) {
    int i = blockIdx.x * 256 + threadIdx.x;
    const int S1 = 256 * KC;
    const int S  = 256 * 256;
    const float* w;
    __half* dst;
    int Kpad, idx;
    if (i < S1)              { w = w1; dst = g_W1; Kpad = KC;  idx = i; }
    else if (i < S1 + S)     { w = w2; dst = g_W2; Kpad = 256; idx = i - S1; }
    else if (i < S1 + 2 * S) { w = w3; dst = g_W3; Kpad = 256; idx = i - S1 - S; }
    else if (i < S1 + 3 * S) { w = w4; dst = g_W4; Kpad = 256; idx = i - S1 - 2 * S; }
    else return;
    int n = idx / Kpad, k = idx - n * Kpad;
    dst[idx] = __float2half_rn(w[(size_t)k * 256 + n]);
}

// ---------------- im2col: per-pixel 3x3 reflect patch -> fp16 hi/lo --------
__global__ void im2col_kernel(const float* __restrict__ F) {
    const int p = blockIdx.x;
    const int t = threadIdx.x;         // 0..287
    const int y0 = p >> 8, x0 = p & 255;
    int c  = t / 9;
    int k  = t - c * 9;
    int di = k / 3, dj = k - di * 3;
    int y = y0 + di - 1;
    int x = x0 + dj - 1;
    y = (y < 0) ? -y : ((y >= HH) ? 2 * HH - 2 - y : y);
    x = (x < 0) ? -x : ((x >= WW) ? 2 * WW - 2 - x : x);
    float v = F[(size_t)c * NPIX + y * WW + x];
    __half h = __float2half_rn(v);
    g_XCh[(size_t)p * KC + t] = h;
    g_XCl[(size_t)p * KC + t] = __float2half_rn(v - __half2float(h));
}

// ---------------- rowinfo ----------------------------------------------------
__global__ __launch_bounds__(256)
void rowinfo_kernel(const float* __restrict__ loc,
                    const float* __restrict__ cell) {
    int i = blockIdx.x * 256 + threadIdx.x;
    int q = i & (Q - 1);
    int s = i >> 16;

    float l0 = loc[(size_t)q * 2 + 0];
    float l1 = loc[(size_t)q * 2 + 1];
    float sy = (s & 2) ? 1.f : -1.f;
    float sx = (s & 1) ? 1.f : -1.f;
    float ly = l0 + sy * (1.f / HH) + 1e-6f;
    float lx = l1 + sx * (1.f / WW) + 1e-6f;
    ly = fminf(fmaxf(ly, -1.f + 1e-6f), 1.f - 1e-6f);
    lx = fminf(fmaxf(lx, -1.f + 1e-6f), 1.f - 1e-6f);
    int iy = (int)rintf(((ly + 1.f) * HH - 1.f) * 0.5f);
    int ix = (int)rintf(((lx + 1.f) * WW - 1.f) * 0.5f);
    iy = min(max(iy, 0), HH - 1);
    ix = min(max(ix, 0), WW - 1);
    float qy = -1.f + (2.f * iy + 1.f) / HH;
    float qx = -1.f + (2.f * ix + 1.f) / WW;
    float rel0 = (l0 - qy) * HH;
    float rel1 = (l1 - qx) * WW;
    float c0 = cell[(size_t)q * 2 + 0] * HH;
    float c1 = cell[(size_t)q * 2 + 1] * WW;

    g_RIP[i]  = iy * WW + ix;
    g_RIV[i]  = make_float4(rel0, rel1, c0, c1);
    g_AREA[i] = fabsf(rel0 * rel1) + 1e-9f;
}

// ---------------- combine2: H1 = relu(G[p] + rank-4 + b1) -> fp16 ----------
__global__ __launch_bounds__(256)
void combine2_kernel(const float* __restrict__ w1,
                     const float* __restrict__ b1,
                     __half* __restrict__ Hh) {
    __shared__ float sw[5 * 256];
    const int tid = threadIdx.x;
    for (int i = tid; i < 1024; i += 256) sw[i] = w1[288 * 256 + i];
    if (tid < 256) sw[1024 + tid] = b1[tid];
    __syncthreads();

    const size_t row = (size_t)blockIdx.x * 4 + (tid >> 6);
    const int c4 = (tid & 63) * 4;

    const int p = g_RIP[row];
    const float4 rc = g_RIV[row];

    float4 g  = *reinterpret_cast<const float4*>(g_G + (size_t)p * NHID + c4);
    float4 wA = *reinterpret_cast<const float4*>(sw + c4);
    float4 wB = *reinterpret_cast<const float4*>(sw + 256 + c4);
    float4 wC = *reinterpret_cast<const float4*>(sw + 512 + c4);
    float4 wD = *reinterpret_cast<const float4*>(sw + 768 + c4);
    float4 bb = *reinterpret_cast<const float4*>(sw + 1024 + c4);

    float v[4];
    v[0] = fmaxf(g.x + rc.x * wA.x + rc.y * wB.x + rc.z * wC.x + rc.w * wD.x + bb.x, 0.f);
    v[1] = fmaxf(g.y + rc.x * wA.y + rc.y * wB.y + rc.z * wC.y + rc.w * wD.y + bb.y, 0.f);
    v[2] = fmaxf(g.z + rc.x * wA.z + rc.y * wB.z + rc.z * wC.z + rc.w * wD.z + bb.z, 0.f);
    v[3] = fmaxf(g.w + rc.x * wA.w + rc.y * wB.w + rc.z * wC.w + rc.w * wD.w + bb.w, 0.f);

    size_t off = row * NHID + c4;
    *reinterpret_cast<uint2*>(Hh + off) = make_uint2(pack2h(v[0], v[1]), pack2h(v[2], v[3]));
}

// ---------------- HMMA GEMM, 128x128 tile, templated BK / TWOA -------------
template<int K, int BK, bool TWOA>
__device__ __forceinline__ void load_stage(
        __half* st,
        const __half* __restrict__ Ah, const __half* __restrict__ Al,
        const __half* __restrict__ B,
        int m0, int n0, int kb, int tid) {
    constexpr int SSTl   = BK + 8;
    constexpr int PLANEl = 128 * SSTl;
    constexpr int CPR    = BK / 8;
    constexpr int ITERS  = 128 * CPR / 256;
#pragma unroll
    for (int i = 0; i < ITERS; ++i) {
        int chunk = tid + i * 256;
        int row = chunk / CPR;
        int c8  = (chunk % CPR) * 8;
        size_t ga = (size_t)(m0 + row) * K + kb + c8;
        size_t gb = (size_t)(n0 + row) * K + kb + c8;
        int so = row * SSTl + c8;
        cp16(st + so, Ah + ga);
        if (TWOA) {
            cp16(st + PLANEl + so,     Al + ga);
            cp16(st + 2 * PLANEl + so, B + gb);
        } else {
            cp16(st + PLANEl + so,     B + gb);
        }
    }
}

// MODE: 0 = fp32 raw out; 1 = bias+relu -> fp16; 2 = bias+relu -> dot w5 -> atomicAdd
template<int K, int BK, int MODE, bool TWOA>
__global__ __launch_bounds__(256, 2)
void hmma_gemm(const __half* __restrict__ Ah,
               const __half* __restrict__ Al,
               const __half* __restrict__ B,
               const float* __restrict__ bias,
               void* __restrict__ Cout,
               const float* __restrict__ w5) {
    extern __shared__ __half smem[];
    constexpr int SSTl   = BK + 8;
    constexpr int PLANEl = 128 * SSTl;
    constexpr int STAGEl = (TWOA ? 3 : 2) * PLANEl;

    const int tid  = threadIdx.x;
    const int lane = tid & 31;
    const int wid  = tid >> 5;
    const int wm   = wid & 3;
    const int wn   = wid >> 2;
    const int m0   = blockIdx.y * 128;
    const int n0   = blockIdx.x * 128;
    const int lr   = lane >> 2;
    const int lq   = lane & 3;
    const int grp  = lane >> 3;
    const int rr   = lane & 7;

    const int a_row = wm * 32 + (grp & 1) * 8 + rr;
    const int a_kb  = (grp >> 1) * 8;
    const int b_row = wn * 64 + (grp >> 1) * 8 + rr;
    const int b_kb  = (grp & 1) * 8;

    float acc[2][8][4];
#pragma unroll
    for (int i = 0; i < 2; ++i)
#pragma unroll
        for (int j = 0; j < 8; ++j)
#pragma unroll
            for (int c = 0; c < 4; ++c) acc[i][j][c] = 0.f;

    constexpr int S = K / BK;
    load_stage<K, BK, TWOA>(smem, Ah, Al, B, m0, n0, 0, tid);
    cp_commit();

    for (int s = 0; s < S; ++s) {
        if (s + 1 < S) {
            load_stage<K, BK, TWOA>(smem + ((s + 1) & 1) * STAGEl, Ah, Al, B,
                                    m0, n0, (s + 1) * BK, tid);
            cp_commit();
            cp_wait<1>();
        } else {
            cp_wait<0>();
        }
        __syncthreads();

        const __half* sAh = smem + (s & 1) * STAGEl;
        const __half* sAl = sAh + PLANEl;                       // TWOA only
        const __half* sB  = sAh + (TWOA ? 2 : 1) * PLANEl;

#pragma unroll
        for (int ks = 0; ks < BK; ks += 16) {
            u32 af[2][2][4];
#pragma unroll
            for (int ti = 0; ti < 2; ++ti) {
                ldsm4(af[ti][0], sAh + (a_row + ti * 16) * SSTl + ks + a_kb);
                if (TWOA)
                    ldsm4(af[ti][1], sAl + (a_row + ti * 16) * SSTl + ks + a_kb);
            }
#pragma unroll
            for (int jp = 0; jp < 4; ++jp) {
                u32 bh[4];
                ldsm4(bh, sB + (b_row + jp * 16) * SSTl + ks + b_kb);
#pragma unroll
                for (int ti = 0; ti < 2; ++ti) {
                    mma_f16(acc[ti][2 * jp],     af[ti][0], bh);
                    mma_f16(acc[ti][2 * jp + 1], af[ti][0], bh + 2);
                }
                if (TWOA) {
#pragma unroll
                    for (int ti = 0; ti < 2; ++ti) {
                        mma_f16(acc[ti][2 * jp],     af[ti][1], bh);
                        mma_f16(acc[ti][2 * jp + 1], af[ti][1], bh + 2);
                    }
                }
            }
        }
        __syncthreads();
    }

    // ---- epilogue ----
    if (MODE == 0) {
        float* C = (float*)Cout;
#pragma unroll
        for (int ti = 0; ti < 2; ++ti) {
            int row0 = m0 + wm * 32 + ti * 16 + lr;
#pragma unroll
            for (int tj = 0; tj < 8; ++tj) {
                int col0 = n0 + wn * 64 + tj * 8 + lq * 2;
#pragma unroll
                for (int half = 0; half < 2; ++half) {
                    size_t off = (size_t)(row0 + half * 8) * NHID + col0;
                    *reinterpret_cast<float2*>(C + off) =
                        make_float2(acc[ti][tj][half * 2 + 0],
                                    acc[ti][tj][half * 2 + 1]);
                }
            }
        }
    } else if (MODE == 1) {
        __half* Chi = (__half*)Cout;
#pragma unroll
        for (int ti = 0; ti < 2; ++ti) {
            int row0 = m0 + wm * 32 + ti * 16 + lr;
#pragma unroll
            for (int tj = 0; tj < 8; ++tj) {
                int col0 = n0 + wn * 64 + tj * 8 + lq * 2;
                float b0 = bias[col0], b1 = bias[col0 + 1];
#pragma unroll
                for (int half = 0; half < 2; ++half) {
                    size_t off = (size_t)(row0 + half * 8) * NHID + col0;
                    float v0 = fmaxf(acc[ti][tj][half * 2 + 0] + b0, 0.f);
                    float v1 = fmaxf(acc[ti][tj][half * 2 + 1] + b1, 0.f);
                    *reinterpret_cast<u32*>(Chi + off) = pack2h(v0, v1);
                }
            }
        }
    } else {
        float part[2][2][3];
#pragma unroll
        for (int ti = 0; ti < 2; ++ti)
#pragma unroll
            for (int h = 0; h < 2; ++h)
#pragma unroll
                for (int c = 0; c < 3; ++c) part[ti][h][c] = 0.f;

#pragma unroll
        for (int tj = 0; tj < 8; ++tj) {
            int col0 = n0 + wn * 64 + tj * 8 + lq * 2;
            float b0 = bias[col0], b1 = bias[col0 + 1];
            float w50[3], w51[3];
#pragma unroll
            for (int c = 0; c < 3; ++c) {
                w50[c] = w5[col0 * 3 + c];
                w51[c] = w5[(col0 + 1) * 3 + c];
            }
#pragma unroll
            for (int ti = 0; ti < 2; ++ti)
#pragma unroll
                for (int half = 0; half < 2; ++half) {
                    float v0 = fmaxf(acc[ti][tj][half * 2 + 0] + b0, 0.f);
                    float v1 = fmaxf(acc[ti][tj][half * 2 + 1] + b1, 0.f);
#pragma unroll
                    for (int c = 0; c < 3; ++c)
                        part[ti][half][c] += v0 * w50[c] + v1 * w51[c];
                }
        }
#pragma unroll
        for (int ti = 0; ti < 2; ++ti)
#pragma unroll
            for (int h = 0; h < 2; ++h)
#pragma unroll
                for (int c = 0; c < 3; ++c) {
                    float v = part[ti][h][c];
                    v += __shfl_xor_sync(0xffffffffu, v, 1);
                    v += __shfl_xor_sync(0xffffffffu, v, 2);
                    part[ti][h][c] = v;
                }
        float* sp = reinterpret_cast<float*>(smem);
        if (lq == 0) {
#pragma unroll
            for (int ti = 0; ti < 2; ++ti)
#pragma unroll
                for (int h = 0; h < 2; ++h) {
                    int row = wm * 32 + ti * 16 + h * 8 + lr;
#pragma unroll
                    for (int c = 0; c < 3; ++c)
                        sp[(wn * 128 + row) * 3 + c] = part[ti][h][c];
                }
        }
        __syncthreads();
        for (int i = tid; i < 384; i += 256) {
            float v = sp[i] + sp[384 + i];
            atomicAdd(&g_PRED[(size_t)(m0 + i / 3) * 3 + (i % 3)], v);
        }
    }
}

// ---------------- output combine --------------------------------------------
__global__ __launch_bounds__(256)
void out_combine(const float* __restrict__ b5, float* __restrict__ out) {
    int q = blockIdx.x * 256 + threadIdx.x;
    float ar[4], tot = 0.f;
#pragma unroll
    for (int s = 0; s < 4; ++s) { ar[s] = g_AREA[(size_t)s * Q + q]; tot += ar[s]; }
    float r0 = 0.f, r1 = 0.f, r2 = 0.f;
#pragma unroll
    for (int s = 0; s < 4; ++s) {
        float wgt = ar[3 - s] / tot;
        size_t base = ((size_t)s * Q + q) * 3;
        r0 += (g_PRED[base + 0] + b5[0]) * wgt;
        r1 += (g_PRED[base + 1] + b5[1]) * wgt;
        r2 += (g_PRED[base + 2] + b5[2]) * wgt;
    }
    out[(size_t)q * 3 + 0] = r0;
    out[(size_t)q * 3 + 1] = r1;
    out[(size_t)q * 3 + 2] = r2;
}

// ---------------- launch ----------------------------------------------------
#define SMEMB_CONV   (2 * 3 * 128 * 40 * 2)   /* 61440: TWOA, BK=32 */
#define SMEMB_HIDDEN (2 * 2 * 128 * 72 * 2)   /* 73728: 1A,  BK=64 */

extern "C" void kernel_launch(void* const* d_in, const int* in_sizes, int n_in,
                              void* d_out, int out_size) {
    const float* F    = (const float*)d_in[0];
    const float* loc  = (const float*)d_in[1];
    const float* cell = (const float*)d_in[2];
    const float* w1 = (const float*)d_in[3];
    const float* b1 = (const float*)d_in[4];
    const float* w2 = (const float*)d_in[5];
    const float* b2 = (const float*)d_in[6];
    const float* w3 = (const float*)d_in[7];
    const float* b3 = (const float*)d_in[8];
    const float* w4 = (const float*)d_in[9];
    const float* b4 = (const float*)d_in[10];
    const float* w5 = (const float*)d_in[11];
    const float* b5 = (const float*)d_in[12];
    float* out = (float*)d_out;

    __half *XCh, *XCl, *HA, *HB;
    __half *W1, *W2, *W3, *W4;
    float *G, *PRED;
    cudaGetSymbolAddress((void**)&XCh, g_XCh); cudaGetSymbolAddress((void**)&XCl, g_XCl);
    cudaGetSymbolAddress((void**)&G,   g_G);
    cudaGetSymbolAddress((void**)&PRED, g_PRED);
    cudaGetSymbolAddress((void**)&HA, g_HA);
    cudaGetSymbolAddress((void**)&HB, g_HB);
    cudaGetSymbolAddress((void**)&W1, g_W1);
    cudaGetSymbolAddress((void**)&W2, g_W2);
    cudaGetSymbolAddress((void**)&W3, g_W3);
    cudaGetSymbolAddress((void**)&W4, g_W4);

    cudaFuncSetAttribute(hmma_gemm<KC, 32, 0, true>,
        cudaFuncAttributeMaxDynamicSharedMemorySize, SMEMB_CONV);
    cudaFuncSetAttribute(hmma_gemm<256, 64, 1, false>,
        cudaFuncAttributeMaxDynamicSharedMemorySize, SMEMB_HIDDEN);
    cudaFuncSetAttribute(hmma_gemm<256, 64, 2, false>,
        cudaFuncAttributeMaxDynamicSharedMemorySize, SMEMB_HIDDEN);

    cudaMemsetAsync(PRED, 0, (size_t)MROWS * 3 * sizeof(float));

    const int PREP_ELEMS = 256 * KC + 3 * 256 * 256;
    prep_all_kernel<<<(PREP_ELEMS + 255) / 256, 256>>>(w1, w2, w3, w4);

    im2col_kernel<<<NPIX, KC>>>(F);
    rowinfo_kernel<<<MROWS / 256, 256>>>(loc, cell);

    // conv GEMM: G[65536,256] = XC @ W1[0:288]^T  (exact-A, 2 products)
    hmma_gemm<KC, 32, 0, true><<<dim3(2, NPIX / 128), 256, SMEMB_CONV>>>(
        XCh, XCl, W1, nullptr, G, nullptr);

    combine2_kernel<<<MROWS / 4, 256>>>(w1, b1, HA);

    dim3 ggrid(2, MROWS / 128);
    hmma_gemm<256, 64, 1, false><<<ggrid, 256, SMEMB_HIDDEN>>>(
        HA, nullptr, W2, b2, HB, nullptr);
    hmma_gemm<256, 64, 1, false><<<ggrid, 256, SMEMB_HIDDEN>>>(
        HB, nullptr, W3, b3, HA, nullptr);
    hmma_gemm<256, 64, 2, false><<<ggrid, 256, SMEMB_HIDDEN>>>(
        HA, nullptr, W4, b4, nullptr, w5);

    out_combine<<<Q / 256, 256>>>(b5, out);
}

// round 15
// speedup vs baseline: 3.5814x; 1.0839x over previous
#include <cuda_runtime.h>
#include <cuda_fp16.h>
#include <cstdint>

#define Q     65536
#define HH    256
#define WW    256
#define NPIX  (HH*WW)    /* 65536 */
#define MROWS (4*Q)      /* 262144 */
#define KC    288
#define NHID  256

typedef unsigned int u32;

// ---------------- scratch (device globals; no allocation allowed) ----------
__device__ __half g_XC [(size_t)NPIX * KC];
__device__ float  g_G  [(size_t)NPIX * NHID];
__device__ __half g_HA [(size_t)MROWS * NHID];
__device__ __half g_HB [(size_t)MROWS * NHID];
__device__ float g_PRED[(size_t)MROWS * 3];
__device__ float g_AREA[MROWS];
__device__ int    g_RIP[MROWS];
__device__ float4 g_RIV[MROWS];
__device__ __half g_W1[256 * KC];
__device__ __half g_W2[256 * 256];
__device__ __half g_W3[256 * 256];
__device__ __half g_W4[256 * 256];

// ---------------- helpers ---------------------------------------------------
__device__ __forceinline__ u32 pack2h(float x, float y) {
    __half2 t = __floats2half2_rn(x, y);
    return *reinterpret_cast<u32*>(&t);
}
__device__ __forceinline__ void mma_f16(float* d, const u32* a, const u32* b) {
    asm("mma.sync.aligned.m16n8k16.row.col.f32.f16.f16.f32 "
        "{%0,%1,%2,%3}, {%4,%5,%6,%7}, {%8,%9}, {%0,%1,%2,%3};"
        : "+f"(d[0]), "+f"(d[1]), "+f"(d[2]), "+f"(d[3])
        : "r"(a[0]), "r"(a[1]), "r"(a[2]), "r"(a[3]), "r"(b[0]), "r"(b[1]));
}
__device__ __forceinline__ void ldsm4(u32* r, const __half* p) {
    u32 a = (u32)__cvta_generic_to_shared(p);
    asm volatile("ldmatrix.sync.aligned.m8n8.x4.shared.b16 {%0,%1,%2,%3}, [%4];"
                 : "=r"(r[0]), "=r"(r[1]), "=r"(r[2]), "=r"(r[3]) : "r"(a));
}
__device__ __forceinline__ void cp16(__half* s, const __half* g) {
    u32 sa = (u32)__cvta_generic_to_shared(s);
    asm volatile("cp.async.cg.shared.global [%0], [%1], 16;" :: "r"(sa), "l"(g));
}
__device__ __forceinline__ void cp_commit() {
    asm volatile("cp.async.commit_group;" ::: "memory");
}
template<int N> __device__ __forceinline__ void cp_wait() {
    asm volatile("cp.async.wait_group %0;" :: "n"(N) : "memory");
}

// ---------------- W prep: transpose -> single fp16 plane --------------------
__global__ void prep_all_kernel(const float* __restrict__ w1,
                                const float* __restrict__ w2,
                                const float* __restrict__ w3,
                                const float* __restrict__ w4) {
    int i = blockIdx.x * 256 + threadIdx.x;
    const int S1 = 256 * KC;
    const int S  = 256 * 256;
    const float* w;
    __half* dst;
    int Kpad, idx;
    if (i < S1)              { w = w1; dst = g_W1; Kpad = KC;  idx = i; }
    else if (i < S1 + S)     { w = w2; dst = g_W2; Kpad = 256; idx = i - S1; }
    else if (i < S1 + 2 * S) { w = w3; dst = g_W3; Kpad = 256; idx = i - S1 - S; }
    else if (i < S1 + 3 * S) { w = w4; dst = g_W4; Kpad = 256; idx = i - S1 - 2 * S; }
    else return;
    int n = idx / Kpad, k = idx - n * Kpad;
    dst[idx] = __float2half_rn(w[(size_t)k * 256 + n]);
}

// ---------------- im2col: per-pixel 3x3 reflect patch -> fp16 ---------------
__global__ void im2col_kernel(const float* __restrict__ F) {
    const int p = blockIdx.x;
    const int t = threadIdx.x;         // 0..287
    const int y0 = p >> 8, x0 = p & 255;
    int c  = t / 9;
    int k  = t - c * 9;
    int di = k / 3, dj = k - di * 3;
    int y = y0 + di - 1;
    int x = x0 + dj - 1;
    y = (y < 0) ? -y : ((y >= HH) ? 2 * HH - 2 - y : y);
    x = (x < 0) ? -x : ((x >= WW) ? 2 * WW - 2 - x : x);
    g_XC[(size_t)p * KC + t] = __float2half_rn(F[(size_t)c * NPIX + y * WW + x]);
}

// ---------------- rowinfo ----------------------------------------------------
__global__ __launch_bounds__(256)
void rowinfo_kernel(const float* __restrict__ loc,
                    const float* __restrict__ cell) {
    int i = blockIdx.x * 256 + threadIdx.x;
    int q = i & (Q - 1);
    int s = i >> 16;

    float l0 = loc[(size_t)q * 2 + 0];
    float l1 = loc[(size_t)q * 2 + 1];
    float sy = (s & 2) ? 1.f : -1.f;
    float sx = (s & 1) ? 1.f : -1.f;
    float ly = l0 + sy * (1.f / HH) + 1e-6f;
    float lx = l1 + sx * (1.f / WW) + 1e-6f;
    ly = fminf(fmaxf(ly, -1.f + 1e-6f), 1.f - 1e-6f);
    lx = fminf(fmaxf(lx, -1.f + 1e-6f), 1.f - 1e-6f);
    int iy = (int)rintf(((ly + 1.f) * HH - 1.f) * 0.5f);
    int ix = (int)rintf(((lx + 1.f) * WW - 1.f) * 0.5f);
    iy = min(max(iy, 0), HH - 1);
    ix = min(max(ix, 0), WW - 1);
    float qy = -1.f + (2.f * iy + 1.f) / HH;
    float qx = -1.f + (2.f * ix + 1.f) / WW;
    float rel0 = (l0 - qy) * HH;
    float rel1 = (l1 - qx) * WW;
    float c0 = cell[(size_t)q * 2 + 0] * HH;
    float c1 = cell[(size_t)q * 2 + 1] * WW;

    g_RIP[i]  = iy * WW + ix;
    g_RIV[i]  = make_float4(rel0, rel1, c0, c1);
    g_AREA[i] = fabsf(rel0 * rel1) + 1e-9f;
}

// ---------------- combine2: H1 = relu(G[p] + rank-4 + b1) -> fp16 ----------
__global__ __launch_bounds__(256)
void combine2_kernel(const float* __restrict__ w1,
                     const float* __restrict__ b1,
                     __half* __restrict__ Hh) {
    __shared__ float sw[5 * 256];
    const int tid = threadIdx.x;
    for (int i = tid; i < 1024; i += 256) sw[i] = w1[288 * 256 + i];
    if (tid < 256) sw[1024 + tid] = b1[tid];
    __syncthreads();

    const size_t row = (size_t)blockIdx.x * 4 + (tid >> 6);
    const int c4 = (tid & 63) * 4;

    const int p = g_RIP[row];
    const float4 rc = g_RIV[row];

    float4 g  = *reinterpret_cast<const float4*>(g_G + (size_t)p * NHID + c4);
    float4 wA = *reinterpret_cast<const float4*>(sw + c4);
    float4 wB = *reinterpret_cast<const float4*>(sw + 256 + c4);
    float4 wC = *reinterpret_cast<const float4*>(sw + 512 + c4);
    float4 wD = *reinterpret_cast<const float4*>(sw + 768 + c4);
    float4 bb = *reinterpret_cast<const float4*>(sw + 1024 + c4);

    float v[4];
    v[0] = fmaxf(g.x + rc.x * wA.x + rc.y * wB.x + rc.z * wC.x + rc.w * wD.x + bb.x, 0.f);
    v[1] = fmaxf(g.y + rc.x * wA.y + rc.y * wB.y + rc.z * wC.y + rc.w * wD.y + bb.y, 0.f);
    v[2] = fmaxf(g.z + rc.x * wA.z + rc.y * wB.z + rc.z * wC.z + rc.w * wD.z + bb.z, 0.f);
    v[3] = fmaxf(g.w + rc.x * wA.w + rc.y * wB.w + rc.z * wC.w + rc.w * wD.w + bb.w, 0.f);

    size_t off = row * NHID + c4;
    *reinterpret_cast<uint2*>(Hh + off) = make_uint2(pack2h(v[0], v[1]), pack2h(v[2], v[3]));
}

// ---------------- HMMA GEMM, 128x128 tile, 3-stage cp.async pipeline -------
template<int K, int BK>
__device__ __forceinline__ void load_stage(
        __half* st,
        const __half* __restrict__ A, const __half* __restrict__ B,
        int m0, int n0, int kb, int tid) {
    constexpr int SSTl   = BK + 8;
    constexpr int PLANEl = 128 * SSTl;
    constexpr int CPR    = BK / 8;
    constexpr int ITERS  = 128 * CPR / 256;
#pragma unroll
    for (int i = 0; i < ITERS; ++i) {
        int chunk = tid + i * 256;
        int row = chunk / CPR;
        int c8  = (chunk % CPR) * 8;
        int so = row * SSTl + c8;
        cp16(st + so,          A + (size_t)(m0 + row) * K + kb + c8);
        cp16(st + PLANEl + so, B + (size_t)(n0 + row) * K + kb + c8);
    }
}

// MODE: 0 = fp32 raw out; 1 = bias+relu -> fp16; 2 = bias+relu -> dot w5 -> atomicAdd
template<int K, int BK, int MODE>
__global__ __launch_bounds__(256, 2)
void hmma_gemm(const __half* __restrict__ A,
               const __half* __restrict__ B,
               const float* __restrict__ bias,
               void* __restrict__ Cout,
               const float* __restrict__ w5) {
    extern __shared__ __half smem[];
    constexpr int SSTl   = BK + 8;
    constexpr int PLANEl = 128 * SSTl;
    constexpr int STAGEl = 2 * PLANEl;

    const int tid  = threadIdx.x;
    const int lane = tid & 31;
    const int wid  = tid >> 5;
    const int wm   = wid & 3;
    const int wn   = wid >> 2;
    const int m0   = blockIdx.y * 128;
    const int n0   = blockIdx.x * 128;
    const int lr   = lane >> 2;
    const int lq   = lane & 3;
    const int grp  = lane >> 3;
    const int rr   = lane & 7;

    const int a_row = wm * 32 + (grp & 1) * 8 + rr;
    const int a_kb  = (grp >> 1) * 8;
    const int b_row = wn * 64 + (grp >> 1) * 8 + rr;
    const int b_kb  = (grp & 1) * 8;

    float acc[2][8][4];
#pragma unroll
    for (int i = 0; i < 2; ++i)
#pragma unroll
        for (int j = 0; j < 8; ++j)
#pragma unroll
            for (int c = 0; c < 4; ++c) acc[i][j][c] = 0.f;

    constexpr int S = K / BK;
    load_stage<K, BK>(smem, A, B, m0, n0, 0, tid);
    cp_commit();
    if (S > 1) {
        load_stage<K, BK>(smem + STAGEl, A, B, m0, n0, BK, tid);
        cp_commit();
    }

    for (int s = 0; s < S; ++s) {
        if (s + 2 < S) {
            load_stage<K, BK>(smem + ((s + 2) % 3) * STAGEl, A, B,
                              m0, n0, (s + 2) * BK, tid);
            cp_commit();
            cp_wait<2>();
        } else if (s + 1 < S) {
            cp_wait<1>();
        } else {
            cp_wait<0>();
        }
        __syncthreads();

        const __half* sA = smem + (s % 3) * STAGEl;
        const __half* sB = sA + PLANEl;

#pragma unroll
        for (int ks = 0; ks < BK; ks += 16) {
            u32 af[2][4];
#pragma unroll
            for (int ti = 0; ti < 2; ++ti)
                ldsm4(af[ti], sA + (a_row + ti * 16) * SSTl + ks + a_kb);
#pragma unroll
            for (int jp = 0; jp < 4; ++jp) {
                u32 bh[4];
                ldsm4(bh, sB + (b_row + jp * 16) * SSTl + ks + b_kb);
#pragma unroll
                for (int ti = 0; ti < 2; ++ti) {
                    mma_f16(acc[ti][2 * jp],     af[ti], bh);
                    mma_f16(acc[ti][2 * jp + 1], af[ti], bh + 2);
                }
            }
        }
        __syncthreads();
    }

    // ---- epilogue ----
    if (MODE == 0) {
        float* C = (float*)Cout;
#pragma unroll
        for (int ti = 0; ti < 2; ++ti) {
            int row0 = m0 + wm * 32 + ti * 16 + lr;
#pragma unroll
            for (int tj = 0; tj < 8; ++tj) {
                int col0 = n0 + wn * 64 + tj * 8 + lq * 2;
#pragma unroll
                for (int half = 0; half < 2; ++half) {
                    size_t off = (size_t)(row0 + half * 8) * NHID + col0;
                    *reinterpret_cast<float2*>(C + off) =
                        make_float2(acc[ti][tj][half * 2 + 0],
                                    acc[ti][tj][half * 2 + 1]);
                }
            }
        }
    } else if (MODE == 1) {
        __half* Chi = (__half*)Cout;
#pragma unroll
        for (int ti = 0; ti < 2; ++ti) {
            int row0 = m0 + wm * 32 + ti * 16 + lr;
#pragma unroll
            for (int tj = 0; tj < 8; ++tj) {
                int col0 = n0 + wn * 64 + tj * 8 + lq * 2;
                float b0 = bias[col0], b1 = bias[col0 + 1];
#pragma unroll
                for (int half = 0; half < 2; ++half) {
                    size_t off = (size_t)(row0 + half * 8) * NHID + col0;
                    float v0 = fmaxf(acc[ti][tj][half * 2 + 0] + b0, 0.f);
                    float v1 = fmaxf(acc[ti][tj][half * 2 + 1] + b1, 0.f);
                    *reinterpret_cast<u32*>(Chi + off) = pack2h(v0, v1);
                }
            }
        }
    } else {
        float part[2][2][3];
#pragma unroll
        for (int ti = 0; ti < 2; ++ti)
#pragma unroll
            for (int h = 0; h < 2; ++h)
#pragma unroll
                for (int c = 0; c < 3; ++c) part[ti][h][c] = 0.f;

#pragma unroll
        for (int tj = 0; tj < 8; ++tj) {
            int col0 = n0 + wn * 64 + tj * 8 + lq * 2;
            float b0 = bias[col0], b1 = bias[col0 + 1];
            float w50[3], w51[3];
#pragma unroll
            for (int c = 0; c < 3; ++c) {
                w50[c] = w5[col0 * 3 + c];
                w51[c] = w5[(col0 + 1) * 3 + c];
            }
#pragma unroll
            for (int ti = 0; ti < 2; ++ti)
#pragma unroll
                for (int half = 0; half < 2; ++half) {
                    float v0 = fmaxf(acc[ti][tj][half * 2 + 0] + b0, 0.f);
                    float v1 = fmaxf(acc[ti][tj][half * 2 + 1] + b1, 0.f);
#pragma unroll
                    for (int c = 0; c < 3; ++c)
                        part[ti][half][c] += v0 * w50[c] + v1 * w51[c];
                }
        }
#pragma unroll
        for (int ti = 0; ti < 2; ++ti)
#pragma unroll
            for (int h = 0; h < 2; ++h)
#pragma unroll
                for (int c = 0; c < 3; ++c) {
                    float v = part[ti][h][c];
                    v += __shfl_xor_sync(0xffffffffu, v, 1);
                    v += __shfl_xor_sync(0xffffffffu, v, 2);
                    part[ti][h][c] = v;
                }
        float* sp = reinterpret_cast<float*>(smem);
        if (lq == 0) {
#pragma unroll
            for (int ti = 0; ti < 2; ++ti)
#pragma unroll
                for (int h = 0; h < 2; ++h) {
                    int row = wm * 32 + ti * 16 + h * 8 + lr;
#pragma unroll
                    for (int c = 0; c < 3; ++c)
                        sp[(wn * 128 + row) * 3 + c] = part[ti][h][c];
                }
        }
        __syncthreads();
        for (int i = tid; i < 384; i += 256) {
            float v = sp[i] + sp[384 + i];
            atomicAdd(&g_PRED[(size_t)(m0 + i / 3) * 3 + (i % 3)], v);
        }
    }
}

// ---------------- output combine --------------------------------------------
__global__ __launch_bounds__(256)
void out_combine(const float* __restrict__ b5, float* __restrict__ out) {
    int q = blockIdx.x * 256 + threadIdx.x;
    float ar[4], tot = 0.f;
#pragma unroll
    for (int s = 0; s < 4; ++s) { ar[s] = g_AREA[(size_t)s * Q + q]; tot += ar[s]; }
    float r0 = 0.f, r1 = 0.f, r2 = 0.f;
#pragma unroll
    for (int s = 0; s < 4; ++s) {
        float wgt = ar[3 - s] / tot;
        size_t base = ((size_t)s * Q + q) * 3;
        r0 += (g_PRED[base + 0] + b5[0]) * wgt;
        r1 += (g_PRED[base + 1] + b5[1]) * wgt;
        r2 += (g_PRED[base + 2] + b5[2]) * wgt;
    }
    out[(size_t)q * 3 + 0] = r0;
    out[(size_t)q * 3 + 1] = r1;
    out[(size_t)q * 3 + 2] = r2;
}

// ---------------- launch ----------------------------------------------------
#define SMEMB_CONV   (3 * 2 * 128 * 40 * 2)   /* 61440:  BK=32, 3 stages */
#define SMEMB_HIDDEN (3 * 2 * 128 * 72 * 2)   /* 110592: BK=64, 3 stages */

extern "C" void kernel_launch(void* const* d_in, const int* in_sizes, int n_in,
                              void* d_out, int out_size) {
    const float* F    = (const float*)d_in[0];
    const float* loc  = (const float*)d_in[1];
    const float* cell = (const float*)d_in[2];
    const float* w1 = (const float*)d_in[3];
    const float* b1 = (const float*)d_in[4];
    const float* w2 = (const float*)d_in[5];
    const float* b2 = (const float*)d_in[6];
    const float* w3 = (const float*)d_in[7];
    const float* b3 = (const float*)d_in[8];
    const float* w4 = (const float*)d_in[9];
    const float* b4 = (const float*)d_in[10];
    const float* w5 = (const float*)d_in[11];
    const float* b5 = (const float*)d_in[12];
    float* out = (float*)d_out;

    __half *XC, *HA, *HB, *W1, *W2, *W3, *W4;
    float *G, *PRED;
    cudaGetSymbolAddress((void**)&XC, g_XC);
    cudaGetSymbolAddress((void**)&G,  g_G);
    cudaGetSymbolAddress((void**)&PRED, g_PRED);
    cudaGetSymbolAddress((void**)&HA, g_HA);
    cudaGetSymbolAddress((void**)&HB, g_HB);
    cudaGetSymbolAddress((void**)&W1, g_W1);
    cudaGetSymbolAddress((void**)&W2, g_W2);
    cudaGetSymbolAddress((void**)&W3, g_W3);
    cudaGetSymbolAddress((void**)&W4, g_W4);

    cudaFuncSetAttribute(hmma_gemm<KC, 32, 0>,
        cudaFuncAttributeMaxDynamicSharedMemorySize, SMEMB_CONV);
    cudaFuncSetAttribute(hmma_gemm<256, 64, 1>,
        cudaFuncAttributeMaxDynamicSharedMemorySize, SMEMB_HIDDEN);
    cudaFuncSetAttribute(hmma_gemm<256, 64, 2>,
        cudaFuncAttributeMaxDynamicSharedMemorySize, SMEMB_HIDDEN);

    cudaMemsetAsync(PRED, 0, (size_t)MROWS * 3 * sizeof(float));

    const int PREP_ELEMS = 256 * KC + 3 * 256 * 256;
    prep_all_kernel<<<(PREP_ELEMS + 255) / 256, 256>>>(w1, w2, w3, w4);

    im2col_kernel<<<NPIX, KC>>>(F);
    rowinfo_kernel<<<MROWS / 256, 256>>>(loc, cell);

    // conv GEMM: G[65536,256] = XC @ W1[0:288]^T
    hmma_gemm<KC, 32, 0><<<dim3(2, NPIX / 128), 256, SMEMB_CONV>>>(
        XC, W1, nullptr, G, nullptr);

    combine2_kernel<<<MROWS / 4, 256>>>(w1, b1, HA);

    dim3 ggrid(2, MROWS / 128);
    hmma_gemm<256, 64, 1><<<ggrid, 256, SMEMB_HIDDEN>>>(HA, W2, b2, HB, nullptr);
    hmma_gemm<256, 64, 1><<<ggrid, 256, SMEMB_HIDDEN>>>(HB, W3, b3, HA, nullptr);
    hmma_gemm<256, 64, 2><<<ggrid, 256, SMEMB_HIDDEN>>>(HA, W4, b4, nullptr, w5);

    out_combine<<<Q / 256, 256>>>(b5, out);
}

// round 16
// speedup vs baseline: 3.6541x; 1.0203x over previous
#include <cuda_runtime.h>
#include <cuda_fp16.h>
#include <cstdint>

#define Q     65536
#define HH    256
#define WW    256
#define NPIX  (HH*WW)    /* 65536 */
#define MROWS (4*Q)      /* 262144 */
#define KC    288
#define NHID  256

typedef unsigned int u32;

// ---------------- scratch (device globals; no allocation allowed) ----------
__device__ __half g_XC [(size_t)NPIX * KC];
__device__ float  g_G  [(size_t)NPIX * NHID];
__device__ __half g_HA [(size_t)MROWS * NHID];
__device__ __half g_HB [(size_t)MROWS * NHID];
__device__ float g_PRED[(size_t)MROWS * 3];
__device__ float g_AREA[MROWS];
__device__ int    g_RIP[MROWS];
__device__ float4 g_RIV[MROWS];
__device__ __half g_W1[256 * KC];
__device__ __half g_W2[256 * 256];
__device__ __half g_W3[256 * 256];
__device__ __half g_W4[256 * 256];

// ---------------- helpers ---------------------------------------------------
__device__ __forceinline__ u32 pack2h(float x, float y) {
    __half2 t = __floats2half2_rn(x, y);
    return *reinterpret_cast<u32*>(&t);
}
__device__ __forceinline__ void mma_f16(float* d, const u32* a, const u32* b) {
    asm("mma.sync.aligned.m16n8k16.row.col.f32.f16.f16.f32 "
        "{%0,%1,%2,%3}, {%4,%5,%6,%7}, {%8,%9}, {%0,%1,%2,%3};"
        : "+f"(d[0]), "+f"(d[1]), "+f"(d[2]), "+f"(d[3])
        : "r"(a[0]), "r"(a[1]), "r"(a[2]), "r"(a[3]), "r"(b[0]), "r"(b[1]));
}
__device__ __forceinline__ void ldsm4(u32* r, const __half* p) {
    u32 a = (u32)__cvta_generic_to_shared(p);
    asm volatile("ldmatrix.sync.aligned.m8n8.x4.shared.b16 {%0,%1,%2,%3}, [%4];"
                 : "=r"(r[0]), "=r"(r[1]), "=r"(r[2]), "=r"(r[3]) : "r"(a));
}
__device__ __forceinline__ void cp16(__half* s, const __half* g) {
    u32 sa = (u32)__cvta_generic_to_shared(s);
    asm volatile("cp.async.cg.shared.global [%0], [%1], 16;" :: "r"(sa), "l"(g));
}
__device__ __forceinline__ void cp_commit() {
    asm volatile("cp.async.commit_group;" ::: "memory");
}
template<int N> __device__ __forceinline__ void cp_wait() {
    asm volatile("cp.async.wait_group %0;" :: "n"(N) : "memory");
}

// ---------------- W prep: transpose -> single fp16 plane --------------------
__global__ void prep_all_kernel(const float* __restrict__ w1,
                                const float* __restrict__ w2,
                                const float* __restrict__ w3,
                                const float* __restrict__ w4) {
    int i = blockIdx.x * 256 + threadIdx.x;
    const int S1 = 256 * KC;
    const int S  = 256 * 256;
    const float* w;
    __half* dst;
    int Kpad, idx;
    if (i < S1)              { w = w1; dst = g_W1; Kpad = KC;  idx = i; }
    else if (i < S1 + S)     { w = w2; dst = g_W2; Kpad = 256; idx = i - S1; }
    else if (i < S1 + 2 * S) { w = w3; dst = g_W3; Kpad = 256; idx = i - S1 - S; }
    else if (i < S1 + 3 * S) { w = w4; dst = g_W4; Kpad = 256; idx = i - S1 - 2 * S; }
    else return;
    int n = idx / Kpad, k = idx - n * Kpad;
    dst[idx] = __float2half_rn(w[(size_t)k * 256 + n]);
}

// ---------------- im2col: per-pixel 3x3 reflect patch -> fp16 ---------------
__global__ void im2col_kernel(const float* __restrict__ F) {
    const int p = blockIdx.x;
    const int t = threadIdx.x;         // 0..287
    const int y0 = p >> 8, x0 = p & 255;
    int c  = t / 9;
    int k  = t - c * 9;
    int di = k / 3, dj = k - di * 3;
    int y = y0 + di - 1;
    int x = x0 + dj - 1;
    y = (y < 0) ? -y : ((y >= HH) ? 2 * HH - 2 - y : y);
    x = (x < 0) ? -x : ((x >= WW) ? 2 * WW - 2 - x : x);
    g_XC[(size_t)p * KC + t] = __float2half_rn(F[(size_t)c * NPIX + y * WW + x]);
}

// ---------------- rowinfo ----------------------------------------------------
__global__ __launch_bounds__(256)
void rowinfo_kernel(const float* __restrict__ loc,
                    const float* __restrict__ cell) {
    int i = blockIdx.x * 256 + threadIdx.x;
    int q = i & (Q - 1);
    int s = i >> 16;

    float l0 = loc[(size_t)q * 2 + 0];
    float l1 = loc[(size_t)q * 2 + 1];
    float sy = (s & 2) ? 1.f : -1.f;
    float sx = (s & 1) ? 1.f : -1.f;
    float ly = l0 + sy * (1.f / HH) + 1e-6f;
    float lx = l1 + sx * (1.f / WW) + 1e-6f;
    ly = fminf(fmaxf(ly, -1.f + 1e-6f), 1.f - 1e-6f);
    lx = fminf(fmaxf(lx, -1.f + 1e-6f), 1.f - 1e-6f);
    int iy = (int)rintf(((ly + 1.f) * HH - 1.f) * 0.5f);
    int ix = (int)rintf(((lx + 1.f) * WW - 1.f) * 0.5f);
    iy = min(max(iy, 0), HH - 1);
    ix = min(max(ix, 0), WW - 1);
    float qy = -1.f + (2.f * iy + 1.f) / HH;
    float qx = -1.f + (2.f * ix + 1.f) / WW;
    float rel0 = (l0 - qy) * HH;
    float rel1 = (l1 - qx) * WW;
    float c0 = cell[(size_t)q * 2 + 0] * HH;
    float c1 = cell[(size_t)q * 2 + 1] * WW;

    g_RIP[i]  = iy * WW + ix;
    g_RIV[i]  = make_float4(rel0, rel1, c0, c1);
    g_AREA[i] = fabsf(rel0 * rel1) + 1e-9f;
}

// ---------------- combine2: H1 = relu(G[p] + rank-4 + b1) -> fp16 ----------
__global__ __launch_bounds__(256)
void combine2_kernel(const float* __restrict__ w1,
                     const float* __restrict__ b1,
                     __half* __restrict__ Hh) {
    __shared__ float sw[5 * 256];
    const int tid = threadIdx.x;
    for (int i = tid; i < 1024; i += 256) sw[i] = w1[288 * 256 + i];
    if (tid < 256) sw[1024 + tid] = b1[tid];
    __syncthreads();

    const size_t row = (size_t)blockIdx.x * 4 + (tid >> 6);
    const int c4 = (tid & 63) * 4;

    const int p = g_RIP[row];
    const float4 rc = g_RIV[row];

    float4 g  = *reinterpret_cast<const float4*>(g_G + (size_t)p * NHID + c4);
    float4 wA = *reinterpret_cast<const float4*>(sw + c4);
    float4 wB = *reinterpret_cast<const float4*>(sw + 256 + c4);
    float4 wC = *reinterpret_cast<const float4*>(sw + 512 + c4);
    float4 wD = *reinterpret_cast<const float4*>(sw + 768 + c4);
    float4 bb = *reinterpret_cast<const float4*>(sw + 1024 + c4);

    float v[4];
    v[0] = fmaxf(g.x + rc.x * wA.x + rc.y * wB.x + rc.z * wC.x + rc.w * wD.x + bb.x, 0.f);
    v[1] = fmaxf(g.y + rc.x * wA.y + rc.y * wB.y + rc.z * wC.y + rc.w * wD.y + bb.y, 0.f);
    v[2] = fmaxf(g.z + rc.x * wA.z + rc.y * wB.z + rc.z * wC.z + rc.w * wD.z + bb.z, 0.f);
    v[3] = fmaxf(g.w + rc.x * wA.w + rc.y * wB.w + rc.z * wC.w + rc.w * wD.w + bb.w, 0.f);

    size_t off = row * NHID + c4;
    *reinterpret_cast<uint2*>(Hh + off) = make_uint2(pack2h(v[0], v[1]), pack2h(v[2], v[3]));
}

// ---------------- HMMA GEMM, 128x128 tile, 3-stage / single-sync loop ------
template<int K, int BK>
__device__ __forceinline__ void load_stage(
        __half* st,
        const __half* __restrict__ A, const __half* __restrict__ B,
        int m0, int n0, int kb, int tid) {
    constexpr int SSTl   = BK + 8;
    constexpr int PLANEl = 128 * SSTl;
    constexpr int CPR    = BK / 8;
    constexpr int ITERS  = 128 * CPR / 256;
#pragma unroll
    for (int i = 0; i < ITERS; ++i) {
        int chunk = tid + i * 256;
        int row = chunk / CPR;
        int c8  = (chunk % CPR) * 8;
        int so = row * SSTl + c8;
        cp16(st + so,          A + (size_t)(m0 + row) * K + kb + c8);
        cp16(st + PLANEl + so, B + (size_t)(n0 + row) * K + kb + c8);
    }
}

// MODE: 0 = fp32 raw out; 1 = bias+relu -> fp16; 2 = bias+relu -> dot w5 -> atomicAdd
template<int K, int BK, int MODE>
__global__ __launch_bounds__(256, 2)
void hmma_gemm(const __half* __restrict__ A,
               const __half* __restrict__ B,
               const float* __restrict__ bias,
               void* __restrict__ Cout,
               const float* __restrict__ w5) {
    extern __shared__ __half smem[];
    constexpr int SSTl   = BK + 8;
    constexpr int PLANEl = 128 * SSTl;
    constexpr int STAGEl = 2 * PLANEl;

    const int tid  = threadIdx.x;
    const int lane = tid & 31;
    const int wid  = tid >> 5;
    const int wm   = wid & 3;
    const int wn   = wid >> 2;
    const int m0   = blockIdx.y * 128;
    const int n0   = blockIdx.x * 128;
    const int lr   = lane >> 2;
    const int lq   = lane & 3;
    const int grp  = lane >> 3;
    const int rr   = lane & 7;

    const int a_row = wm * 32 + (grp & 1) * 8 + rr;
    const int a_kb  = (grp >> 1) * 8;
    const int b_row = wn * 64 + (grp >> 1) * 8 + rr;
    const int b_kb  = (grp & 1) * 8;

    float acc[2][8][4];
#pragma unroll
    for (int i = 0; i < 2; ++i)
#pragma unroll
        for (int j = 0; j < 8; ++j)
#pragma unroll
            for (int c = 0; c < 4; ++c) acc[i][j][c] = 0.f;

    constexpr int S = K / BK;
    load_stage<K, BK>(smem, A, B, m0, n0, 0, tid);
    cp_commit();
    if (S > 1) {
        load_stage<K, BK>(smem + STAGEl, A, B, m0, n0, BK, tid);
        cp_commit();
    }

    // single-sync pipeline: wait(s) -> sync -> issue load(s+2) -> compute(s)
    for (int s = 0; s < S; ++s) {
        if (s + 1 < S) cp_wait<1>(); else cp_wait<0>();
        __syncthreads();
        if (s + 2 < S) {
            load_stage<K, BK>(smem + ((s + 2) % 3) * STAGEl, A, B,
                              m0, n0, (s + 2) * BK, tid);
            cp_commit();
        }

        const __half* sA = smem + (s % 3) * STAGEl;
        const __half* sB = sA + PLANEl;

#pragma unroll
        for (int ks = 0; ks < BK; ks += 16) {
            u32 af[2][4];
#pragma unroll
            for (int ti = 0; ti < 2; ++ti)
                ldsm4(af[ti], sA + (a_row + ti * 16) * SSTl + ks + a_kb);
#pragma unroll
            for (int jp = 0; jp < 4; ++jp) {
                u32 bh[4];
                ldsm4(bh, sB + (b_row + jp * 16) * SSTl + ks + b_kb);
#pragma unroll
                for (int ti = 0; ti < 2; ++ti) {
                    mma_f16(acc[ti][2 * jp],     af[ti], bh);
                    mma_f16(acc[ti][2 * jp + 1], af[ti], bh + 2);
                }
            }
        }
    }

    // ---- epilogue ----
    if (MODE == 0) {
        float* C = (float*)Cout;
#pragma unroll
        for (int ti = 0; ti < 2; ++ti) {
            int row0 = m0 + wm * 32 + ti * 16 + lr;
#pragma unroll
            for (int tj = 0; tj < 8; ++tj) {
                int col0 = n0 + wn * 64 + tj * 8 + lq * 2;
#pragma unroll
                for (int half = 0; half < 2; ++half) {
                    size_t off = (size_t)(row0 + half * 8) * NHID + col0;
                    *reinterpret_cast<float2*>(C + off) =
                        make_float2(acc[ti][tj][half * 2 + 0],
                                    acc[ti][tj][half * 2 + 1]);
                }
            }
        }
    } else if (MODE == 1) {
        __half* Chi = (__half*)Cout;
#pragma unroll
        for (int ti = 0; ti < 2; ++ti) {
            int row0 = m0 + wm * 32 + ti * 16 + lr;
#pragma unroll
            for (int tj = 0; tj < 8; ++tj) {
                int col0 = n0 + wn * 64 + tj * 8 + lq * 2;
                float b0 = bias[col0], b1 = bias[col0 + 1];
#pragma unroll
                for (int half = 0; half < 2; ++half) {
                    size_t off = (size_t)(row0 + half * 8) * NHID + col0;
                    float v0 = fmaxf(acc[ti][tj][half * 2 + 0] + b0, 0.f);
                    float v1 = fmaxf(acc[ti][tj][half * 2 + 1] + b1, 0.f);
                    *reinterpret_cast<u32*>(Chi + off) = pack2h(v0, v1);
                }
            }
        }
    } else {
        float part[2][2][3];
#pragma unroll
        for (int ti = 0; ti < 2; ++ti)
#pragma unroll
            for (int h = 0; h < 2; ++h)
#pragma unroll
                for (int c = 0; c < 3; ++c) part[ti][h][c] = 0.f;

#pragma unroll
        for (int tj = 0; tj < 8; ++tj) {
            int col0 = n0 + wn * 64 + tj * 8 + lq * 2;
            float b0 = bias[col0], b1 = bias[col0 + 1];
            float w50[3], w51[3];
#pragma unroll
            for (int c = 0; c < 3; ++c) {
                w50[c] = w5[col0 * 3 + c];
                w51[c] = w5[(col0 + 1) * 3 + c];
            }
#pragma unroll
            for (int ti = 0; ti < 2; ++ti)
#pragma unroll
                for (int half = 0; half < 2; ++half) {
                    float v0 = fmaxf(acc[ti][tj][half * 2 + 0] + b0, 0.f);
                    float v1 = fmaxf(acc[ti][tj][half * 2 + 1] + b1, 0.f);
#pragma unroll
                    for (int c = 0; c < 3; ++c)
                        part[ti][half][c] += v0 * w50[c] + v1 * w51[c];
                }
        }
#pragma unroll
        for (int ti = 0; ti < 2; ++ti)
#pragma unroll
            for (int h = 0; h < 2; ++h)
#pragma unroll
                for (int c = 0; c < 3; ++c) {
                    float v = part[ti][h][c];
                    v += __shfl_xor_sync(0xffffffffu, v, 1);
                    v += __shfl_xor_sync(0xffffffffu, v, 2);
                    part[ti][h][c] = v;
                }
        __syncthreads();   // all warps done with mainloop SMEM before reuse
        float* sp = reinterpret_cast<float*>(smem);
        if (lq == 0) {
#pragma unroll
            for (int ti = 0; ti < 2; ++ti)
#pragma unroll
                for (int h = 0; h < 2; ++h) {
                    int row = wm * 32 + ti * 16 + h * 8 + lr;
#pragma unroll
                    for (int c = 0; c < 3; ++c)
                        sp[(wn * 128 + row) * 3 + c] = part[ti][h][c];
                }
        }
        __syncthreads();
        for (int i = tid; i < 384; i += 256) {
            float v = sp[i] + sp[384 + i];
            atomicAdd(&g_PRED[(size_t)(m0 + i / 3) * 3 + (i % 3)], v);
        }
    }
}

// ---------------- output combine --------------------------------------------
__global__ __launch_bounds__(256)
void out_combine(const float* __restrict__ b5, float* __restrict__ out) {
    int q = blockIdx.x * 256 + threadIdx.x;
    float ar[4], tot = 0.f;
#pragma unroll
    for (int s = 0; s < 4; ++s) { ar[s] = g_AREA[(size_t)s * Q + q]; tot += ar[s]; }
    float r0 = 0.f, r1 = 0.f, r2 = 0.f;
#pragma unroll
    for (int s = 0; s < 4; ++s) {
        float wgt = ar[3 - s] / tot;
        size_t base = ((size_t)s * Q + q) * 3;
        r0 += (g_PRED[base + 0] + b5[0]) * wgt;
        r1 += (g_PRED[base + 1] + b5[1]) * wgt;
        r2 += (g_PRED[base + 2] + b5[2]) * wgt;
    }
    out[(size_t)q * 3 + 0] = r0;
    out[(size_t)q * 3 + 1] = r1;
    out[(size_t)q * 3 + 2] = r2;
}

// ---------------- launch ----------------------------------------------------
#define SMEMB_CONV   (3 * 2 * 128 * 40 * 2)   /* 61440:  BK=32, 3 stages */
#define SMEMB_HIDDEN (3 * 2 * 128 * 72 * 2)   /* 110592: BK=64, 3 stages */

extern "C" void kernel_launch(void* const* d_in, const int* in_sizes, int n_in,
                              void* d_out, int out_size) {
    const float* F    = (const float*)d_in[0];
    const float* loc  = (const float*)d_in[1];
    const float* cell = (const float*)d_in[2];
    const float* w1 = (const float*)d_in[3];
    const float* b1 = (const float*)d_in[4];
    const float* w2 = (const float*)d_in[5];
    const float* b2 = (const float*)d_in[6];
    const float* w3 = (const float*)d_in[7];
    const float* b3 = (const float*)d_in[8];
    const float* w4 = (const float*)d_in[9];
    const float* b4 = (const float*)d_in[10];
    const float* w5 = (const float*)d_in[11];
    const float* b5 = (const float*)d_in[12];
    float* out = (float*)d_out;

    __half *XC, *HA, *HB, *W1, *W2, *W3, *W4;
    float *G, *PRED;
    cudaGetSymbolAddress((void**)&XC, g_XC);
    cudaGetSymbolAddress((void**)&G,  g_G);
    cudaGetSymbolAddress((void**)&PRED, g_PRED);
    cudaGetSymbolAddress((void**)&HA, g_HA);
    cudaGetSymbolAddress((void**)&HB, g_HB);
    cudaGetSymbolAddress((void**)&W1, g_W1);
    cudaGetSymbolAddress((void**)&W2, g_W2);
    cudaGetSymbolAddress((void**)&W3, g_W3);
    cudaGetSymbolAddress((void**)&W4, g_W4);

    cudaFuncSetAttribute(hmma_gemm<KC, 32, 0>,
        cudaFuncAttributeMaxDynamicSharedMemorySize, SMEMB_CONV);
    cudaFuncSetAttribute(hmma_gemm<256, 64, 1>,
        cudaFuncAttributeMaxDynamicSharedMemorySize, SMEMB_HIDDEN);
    cudaFuncSetAttribute(hmma_gemm<256, 64, 2>,
        cudaFuncAttributeMaxDynamicSharedMemorySize, SMEMB_HIDDEN);

    cudaMemsetAsync(PRED, 0, (size_t)MROWS * 3 * sizeof(float));

    const int PREP_ELEMS = 256 * KC + 3 * 256 * 256;
    prep_all_kernel<<<(PREP_ELEMS + 255) / 256, 256>>>(w1, w2, w3, w4);

    im2col_kernel<<<NPIX, KC>>>(F);
    rowinfo_kernel<<<MROWS / 256, 256>>>(loc, cell);

    // conv GEMM: G[65536,256] = XC @ W1[0:288]^T
    hmma_gemm<KC, 32, 0><<<dim3(2, NPIX / 128), 256, SMEMB_CONV>>>(
        XC, W1, nullptr, G, nullptr);

    combine2_kernel<<<MROWS / 4, 256>>>(w1, b1, HA);

    dim3 ggrid(2, MROWS / 128);
    hmma_gemm<256, 64, 1><<<ggrid, 256, SMEMB_HIDDEN>>>(HA, W2, b2, HB, nullptr);
    hmma_gemm<256, 64, 1><<<ggrid, 256, SMEMB_HIDDEN>>>(HB, W3, b3, HA, nullptr);
    hmma_gemm<256, 64, 2><<<ggrid, 256, SMEMB_HIDDEN>>>(HA, W4, b4, nullptr, w5);

    out_combine<<<Q / 256, 256>>>(b5, out);
}